// round 1
// baseline (speedup 1.0000x reference)
#include <cuda_runtime.h>
#include <math.h>

#define NN 50000
#define NE 800000
#define HD 128
#define FNI 8
#define FEI 4

// ---------------- device scratch (no allocations allowed) ----------------
__device__ int   g_deg[NN];
__device__ float g_dinv[NN];
__device__ float g_t[NN*HD];   // transform buffer / U
__device__ float g_h1[NN*HD];  // h accumulator A
__device__ float g_h2[NN*HD];  // h accumulator B / V
__device__ float g_M[HD*HD];   // We2 @ Wc1[256:384]
__device__ float g_c1p[HD];    // bc1 + be2 @ Wc1[256:384]

// ---------------- degree / norm ----------------
__global__ void k_deg_zero() {
    int i = blockIdx.x*blockDim.x + threadIdx.x;
    if (i < NN) g_deg[i] = 0;
}
__global__ void k_deg_count(const int* __restrict__ col) {
    int i = blockIdx.x*blockDim.x + threadIdx.x;
    if (i < NE) atomicAdd(&g_deg[col[i]], 1);
}
__global__ void k_dinv() {
    int i = blockIdx.x*blockDim.x + threadIdx.x;
    if (i < NN) g_dinv[i] = rsqrtf((float)(g_deg[i] + 1));  // +1 self loop
}

// ---------------- precompute M = We2 @ Wc1c, c1p = bc1 + be2 @ Wc1c ----------------
__global__ void k_prep(const float* __restrict__ We2, const float* __restrict__ Wc1,
                       const float* __restrict__ be2, const float* __restrict__ bc1) {
    int idx = blockIdx.x*256 + threadIdx.x;   // 0..16383
    int k = idx >> 7, n = idx & 127;
    const float* Wc1c = Wc1 + 256*HD;
    float s = 0.f;
    for (int j = 0; j < HD; j++) s += __ldg(We2 + k*HD + j) * __ldg(Wc1c + j*HD + n);
    g_M[k*HD + n] = s;
    if (k == 0) {
        float c = __ldg(bc1 + n);
        for (int j = 0; j < HD; j++) c += __ldg(be2 + j) * __ldg(Wc1c + j*HD + n);
        g_c1p[n] = c;
    }
}

// ---------------- layer-1 transform (K=8): t = x@W1, selfout = dinv^2 * t ----------------
__global__ void k_transform1(const float* __restrict__ x, const float* __restrict__ W1,
                             float* __restrict__ tout, float* __restrict__ selfout) {
    __shared__ float sx[64*FNI];
    __shared__ float sw[FNI*HD];
    int j = threadIdx.x;  // 0..127
    for (int i = j; i < FNI*HD; i += 128) sw[i] = W1[i];
    int r0 = blockIdx.x * 64;
    for (int i = j; i < 64*FNI; i += 128) {
        int r = r0 + (i >> 3);
        sx[i] = (r < NN) ? x[r*FNI + (i & 7)] : 0.f;
    }
    __syncthreads();
    int mmax = min(64, NN - r0);
    for (int m = 0; m < mmax; m++) {
        int r = r0 + m;
        float acc = 0.f;
        #pragma unroll
        for (int k = 0; k < FNI; k++) acc += sx[m*FNI + k] * sw[k*HD + j];
        float d = g_dinv[r];
        tout[r*HD + j]   = acc;
        selfout[r*HD + j] = d*d*acc;
    }
}

// ---------------- node GEMM (K=128): tout = A@W; optional selfout = dinv^2 * tout ----------------
__global__ __launch_bounds__(256) void k_node_gemm(const float* __restrict__ A,
        const float* __restrict__ W, float* __restrict__ tout, float* __restrict__ selfout) {
    __shared__ float sA[64*HD];   // 32KB
    int tid = threadIdx.x, ty = tid >> 4, tx = tid & 15;
    int r0 = blockIdx.x * 64;
    float4* sA4 = (float4*)sA;
    float4 z4; z4.x = z4.y = z4.z = z4.w = 0.f;
    for (int i = tid; i < 64*32; i += 256) {
        int m = i >> 5, q = i & 31; int r = r0 + m;
        sA4[i] = (r < NN) ? __ldg(((const float4*)A) + (size_t)r*32 + q) : z4;
    }
    __syncthreads();
    float acc[4][8];
    #pragma unroll
    for (int i = 0; i < 4; i++)
        #pragma unroll
        for (int j = 0; j < 8; j++) acc[i][j] = 0.f;
    const float4* W4 = (const float4*)W;
    #pragma unroll 4
    for (int k = 0; k < HD; k++) {
        float a0 = sA[(ty*4+0)*HD + k];
        float a1 = sA[(ty*4+1)*HD + k];
        float a2 = sA[(ty*4+2)*HD + k];
        float a3 = sA[(ty*4+3)*HD + k];
        float4 b0 = __ldg(W4 + k*32 + tx*2);
        float4 b1 = __ldg(W4 + k*32 + tx*2 + 1);
        float bb[8] = {b0.x,b0.y,b0.z,b0.w,b1.x,b1.y,b1.z,b1.w};
        #pragma unroll
        for (int j = 0; j < 8; j++) {
            acc[0][j] += a0*bb[j];
            acc[1][j] += a1*bb[j];
            acc[2][j] += a2*bb[j];
            acc[3][j] += a3*bb[j];
        }
    }
    #pragma unroll
    for (int i = 0; i < 4; i++) {
        int r = r0 + ty*4 + i;
        if (r >= NN) break;
        float d = g_dinv[r]; float dd = d*d;
        size_t base = (size_t)r*HD + tx*8;
        #pragma unroll
        for (int j = 0; j < 8; j++) {
            float v = acc[i][j];
            tout[base + j] = v;
            if (selfout) selfout[base + j] = dd * v;
        }
    }
}

// ---------------- edge scatter: out[col] += dinv[row]*dinv[col] * t[row] ----------------
__global__ void k_scatter(const int* __restrict__ row, const int* __restrict__ col,
                          const float* __restrict__ t, float* __restrict__ out) {
    int gid = blockIdx.x*blockDim.x + threadIdx.x;
    int e = gid >> 5;
    if (e >= NE) return;
    int lane = gid & 31;
    int r = __ldg(row + e), c = __ldg(col + e);
    float w = g_dinv[r] * g_dinv[c];
    float4 v = __ldg(((const float4*)t) + (size_t)r*32 + lane);
    float* dst = out + (size_t)c*HD + lane*4;
    asm volatile("red.global.add.v4.f32 [%0], {%1,%2,%3,%4};"
                 :: "l"(dst), "f"(v.x*w), "f"(v.y*w), "f"(v.z*w), "f"(v.w*w) : "memory");
}

// ---------------- finalize: h = relu(h + b) ----------------
__global__ void k_finalize(float* __restrict__ h, const float* __restrict__ b) {
    int i = blockIdx.x*blockDim.x + threadIdx.x;
    if (i < NN*HD) {
        float v = h[i] + __ldg(b + (i & 127));
        h[i] = fmaxf(v, 0.f);
    }
}

// ---------------- fused edge MLP ----------------
// z1 = relu(U[row] + V[col] + relu(ea@We1+be1)@M + c1p)
// z2 = relu(z1@Wc2 + bc2); logits = z2@Wc3 + bc3; out = log_softmax
#define SMEM_EDGE_BYTES ((24832)*4 + 128*4)   // sA 8192f + sB 16384f + sEA 256f + sIdx 128i

__global__ __launch_bounds__(256, 2) void k_edge_mlp(
        const int* __restrict__ row, const int* __restrict__ col,
        const float* __restrict__ ea,
        const float* __restrict__ We1, const float* __restrict__ be1,
        const float* __restrict__ Wc2, const float* __restrict__ bc2,
        const float* __restrict__ Wc3, const float* __restrict__ bc3,
        const float* __restrict__ U, const float* __restrict__ V,
        float* __restrict__ out) {
    extern __shared__ float sm[];
    float* sA  = sm;             // 8192 floats
    float* sB  = sm + 8192;      // 16384 floats
    float* sEA = sm + 24576;     // 256 floats
    int*   sIdx = (int*)(sm + 24832);  // 128 ints
    int tid = threadIdx.x, ty = tid >> 4, tx = tid & 15;
    int e0 = blockIdx.x * 64;

    if (tid < 64) {
        sIdx[tid]      = __ldg(row + e0 + tid);
        sIdx[64 + tid] = __ldg(col + e0 + tid);
    }
    sEA[tid] = __ldg(ea + (size_t)e0*4 + tid);
    for (int i = tid; i < 16384/4; i += 256)
        ((float4*)sB)[i] = __ldg(((const float4*)g_M) + i);
    __syncthreads();

    // a_tile = relu(ea@We1 + be1) -> sA[64][128]
    for (int i = tid; i < 64*HD; i += 256) {
        int m = i >> 7, j = i & 127;
        float a = __ldg(be1 + j);
        #pragma unroll
        for (int k = 0; k < 4; k++) a += sEA[m*4 + k] * __ldg(We1 + k*HD + j);
        sA[i] = fmaxf(a, 0.f);
    }
    __syncthreads();

    // z = a_tile @ M
    float z[4][8];
    #pragma unroll
    for (int i = 0; i < 4; i++)
        #pragma unroll
        for (int j = 0; j < 8; j++) z[i][j] = 0.f;
    #pragma unroll 4
    for (int k = 0; k < HD; k++) {
        float a0 = sA[(ty*4+0)*HD + k];
        float a1 = sA[(ty*4+1)*HD + k];
        float a2 = sA[(ty*4+2)*HD + k];
        float a3 = sA[(ty*4+3)*HD + k];
        float4 b0 = ((const float4*)sB)[k*32 + tx*2];
        float4 b1 = ((const float4*)sB)[k*32 + tx*2 + 1];
        float bb[8] = {b0.x,b0.y,b0.z,b0.w,b1.x,b1.y,b1.z,b1.w};
        #pragma unroll
        for (int j = 0; j < 8; j++) {
            z[0][j] += a0*bb[j];
            z[1][j] += a1*bb[j];
            z[2][j] += a2*bb[j];
            z[3][j] += a3*bb[j];
        }
    }
    // + U[row] + V[col]
    #pragma unroll
    for (int i = 0; i < 4; i++) {
        int m = ty*4 + i;
        int r = sIdx[m], c = sIdx[64 + m];
        const float4* Up = (const float4*)(U + (size_t)r*HD + tx*8);
        const float4* Vp = (const float4*)(V + (size_t)c*HD + tx*8);
        float4 u0 = __ldg(Up), u1 = __ldg(Up+1), v0 = __ldg(Vp), v1 = __ldg(Vp+1);
        z[i][0] += u0.x + v0.x;  z[i][1] += u0.y + v0.y;
        z[i][2] += u0.z + v0.z;  z[i][3] += u0.w + v0.w;
        z[i][4] += u1.x + v1.x;  z[i][5] += u1.y + v1.y;
        z[i][6] += u1.z + v1.z;  z[i][7] += u1.w + v1.w;
    }
    __syncthreads();   // all reads of sA (a_tile) and sB (M) done

    // z1 = relu(z + c1p) -> sA[64][128]; load Wc2 -> sB
    #pragma unroll
    for (int i = 0; i < 4; i++) {
        int m = ty*4 + i;
        #pragma unroll
        for (int j = 0; j < 8; j++) {
            int n = tx*8 + j;
            sA[m*HD + n] = fmaxf(z[i][j] + g_c1p[n], 0.f);
        }
    }
    for (int i = tid; i < (HD*64)/4; i += 256)
        ((float4*)sB)[i] = __ldg(((const float4*)Wc2) + i);
    __syncthreads();

    // z2 = relu(z1 @ Wc2 + bc2), Wc2 is [128][64]
    float acc2[4][4];
    #pragma unroll
    for (int i = 0; i < 4; i++)
        #pragma unroll
        for (int j = 0; j < 4; j++) acc2[i][j] = 0.f;
    #pragma unroll 4
    for (int k = 0; k < HD; k++) {
        float a0 = sA[(ty*4+0)*HD + k];
        float a1 = sA[(ty*4+1)*HD + k];
        float a2 = sA[(ty*4+2)*HD + k];
        float a3 = sA[(ty*4+3)*HD + k];
        float4 b = ((const float4*)sB)[k*16 + tx];
        acc2[0][0] += a0*b.x; acc2[0][1] += a0*b.y; acc2[0][2] += a0*b.z; acc2[0][3] += a0*b.w;
        acc2[1][0] += a1*b.x; acc2[1][1] += a1*b.y; acc2[1][2] += a1*b.z; acc2[1][3] += a1*b.w;
        acc2[2][0] += a2*b.x; acc2[2][1] += a2*b.y; acc2[2][2] += a2*b.z; acc2[2][3] += a2*b.w;
        acc2[3][0] += a3*b.x; acc2[3][1] += a3*b.y; acc2[3][2] += a3*b.z; acc2[3][3] += a3*b.w;
    }
    __syncthreads();   // reads of sA done; reuse as z2 staging (stride 65, no bank conflicts)

    #pragma unroll
    for (int i = 0; i < 4; i++) {
        int m = ty*4 + i;
        #pragma unroll
        for (int j = 0; j < 4; j++) {
            int n = tx*4 + j;
            sA[m*65 + n] = fmaxf(acc2[i][j] + __ldg(bc2 + n), 0.f);
        }
    }
    __syncthreads();

    if (tid < 64) {
        float l0 = __ldg(bc3 + 0), l1 = __ldg(bc3 + 1);
        #pragma unroll 8
        for (int k = 0; k < 64; k++) {
            float v = sA[tid*65 + k];
            l0 += v * __ldg(Wc3 + 2*k);
            l1 += v * __ldg(Wc3 + 2*k + 1);
        }
        float mx = fmaxf(l0, l1);
        float lse = mx + logf(expf(l0 - mx) + expf(l1 - mx));
        size_t o = (size_t)(e0 + tid) * 2;
        out[o + 0] = l0 - lse;
        out[o + 1] = l1 - lse;
    }
}

// ---------------- launch ----------------
extern "C" void kernel_launch(void* const* d_in, const int* in_sizes, int n_in,
                              void* d_out, int out_size) {
    const float* x   = (const float*)d_in[0];
    const int*   ei  = (const int*)  d_in[1];
    const float* ea  = (const float*)d_in[2];
    const float* W1  = (const float*)d_in[3];
    const float* b1  = (const float*)d_in[4];
    const float* W2  = (const float*)d_in[5];
    const float* b2  = (const float*)d_in[6];
    const float* W3  = (const float*)d_in[7];
    const float* b3  = (const float*)d_in[8];
    const float* We1 = (const float*)d_in[9];
    const float* be1 = (const float*)d_in[10];
    // We2 folded into g_M
    const float* We2 = (const float*)d_in[11];
    const float* be2 = (const float*)d_in[12];
    const float* Wc1 = (const float*)d_in[13];
    const float* bc1 = (const float*)d_in[14];
    const float* Wc2 = (const float*)d_in[15];
    const float* bc2 = (const float*)d_in[16];
    const float* Wc3 = (const float*)d_in[17];
    const float* bc3 = (const float*)d_in[18];
    float* out = (float*)d_out;
    const int* row = ei;
    const int* col = ei + NE;

    float *h1, *h2, *t;
    cudaGetSymbolAddress((void**)&h1, g_h1);
    cudaGetSymbolAddress((void**)&h2, g_h2);
    cudaGetSymbolAddress((void**)&t,  g_t);

    k_deg_zero <<<(NN + 255)/256, 256>>>();
    k_deg_count<<<(NE + 255)/256, 256>>>(col);
    k_dinv     <<<(NN + 255)/256, 256>>>();
    k_prep     <<<64, 256>>>(We2, Wc1, be2, bc1);

    // layer 1
    k_transform1<<<(NN + 63)/64, 128>>>(x, W1, t, h1);
    k_scatter   <<<(NE*32 + 255)/256, 256>>>(row, col, t, h1);
    k_finalize  <<<(NN*HD + 255)/256, 256>>>(h1, b1);
    // layer 2
    k_node_gemm <<<(NN + 63)/64, 256>>>(h1, W2, t, h2);
    k_scatter   <<<(NE*32 + 255)/256, 256>>>(row, col, t, h2);
    k_finalize  <<<(NN*HD + 255)/256, 256>>>(h2, b2);
    // layer 3
    k_node_gemm <<<(NN + 63)/64, 256>>>(h2, W3, t, h1);
    k_scatter   <<<(NE*32 + 255)/256, 256>>>(row, col, t, h1);
    k_finalize  <<<(NN*HD + 255)/256, 256>>>(h1, b3);

    // U = h@Wc1[0:128] -> t,  V = h@Wc1[128:256] -> h2
    k_node_gemm <<<(NN + 63)/64, 256>>>(h1, Wc1,         t,  nullptr);
    k_node_gemm <<<(NN + 63)/64, 256>>>(h1, Wc1 + HD*HD, h2, nullptr);

    cudaFuncSetAttribute(k_edge_mlp, cudaFuncAttributeMaxDynamicSharedMemorySize, SMEM_EDGE_BYTES);
    k_edge_mlp<<<NE/64, 256, SMEM_EDGE_BYTES>>>(row, col, ea, We1, be1,
                                                Wc2, bc2, Wc3, bc3, t, h2, out);
}

// round 4
// speedup vs baseline: 1.9601x; 1.9601x over previous
#include <cuda_runtime.h>
#include <cuda_bf16.h>
#include <math.h>
#include <stdint.h>

#define NN 50000
#define NE 800000
#define HD 128
#define FNI 8
#define FEI 4
#define EB 128   // edges per block in edge MLP

// ---------------- device scratch (no allocations allowed) ----------------
__device__ int   g_deg[NN];
__device__ float g_dinv[NN];
__device__ float g_t[NN*HD];   // transform buffer / U
__device__ float g_h1[NN*HD];  // h accumulator A
__device__ float g_h2[NN*HD];  // h accumulator B / V
__device__ float g_c1p[HD];    // bc1 + be2 @ Wc1[256:384]
__device__ __nv_bfloat16 g_B1[HD*HD];  // M = We2@Wc1c, row-major [k][n], bf16
__device__ __nv_bfloat16 g_B2[HD*64];  // Wc2 row-major [k][n], bf16

// ---------------- PTX helpers ----------------
__device__ __forceinline__ uint32_t smem_u32(const void* p) {
    uint32_t a;
    asm("{ .reg .u64 t; cvta.to.shared.u64 t, %1; cvt.u32.u64 %0, t; }" : "=r"(a) : "l"(p));
    return a;
}
__device__ __forceinline__ void ldsm_x4(uint32_t* r, uint32_t addr) {
    asm volatile("ldmatrix.sync.aligned.m8n8.x4.shared.b16 {%0,%1,%2,%3}, [%4];"
        : "=r"(r[0]), "=r"(r[1]), "=r"(r[2]), "=r"(r[3]) : "r"(addr));
}
__device__ __forceinline__ void ldsm_x4_t(uint32_t* r, uint32_t addr) {
    asm volatile("ldmatrix.sync.aligned.m8n8.x4.trans.shared.b16 {%0,%1,%2,%3}, [%4];"
        : "=r"(r[0]), "=r"(r[1]), "=r"(r[2]), "=r"(r[3]) : "r"(addr));
}
__device__ __forceinline__ void mma_bf16(float* d, const uint32_t* a, uint32_t b0, uint32_t b1) {
    asm volatile("mma.sync.aligned.m16n8k16.row.col.f32.bf16.bf16.f32 "
        "{%0,%1,%2,%3}, {%4,%5,%6,%7}, {%8,%9}, {%0,%1,%2,%3};"
        : "+f"(d[0]), "+f"(d[1]), "+f"(d[2]), "+f"(d[3])
        : "r"(a[0]), "r"(a[1]), "r"(a[2]), "r"(a[3]), "r"(b0), "r"(b1));
}
__device__ __forceinline__ uint32_t pack_bf16x2(float lo, float hi) {
    uint32_t p;
    asm("cvt.rn.bf16x2.f32 %0, %1, %2;" : "=r"(p) : "f"(hi), "f"(lo));
    return p;
}

// ---------------- degree / norm ----------------
__global__ void k_deg_zero() {
    int i = blockIdx.x*blockDim.x + threadIdx.x;
    if (i < NN) g_deg[i] = 0;
}
__global__ void k_deg_count(const int* __restrict__ col) {
    int i = blockIdx.x*blockDim.x + threadIdx.x;
    if (i < NE) atomicAdd(&g_deg[col[i]], 1);
}
__global__ void k_dinv() {
    int i = blockIdx.x*blockDim.x + threadIdx.x;
    if (i < NN) g_dinv[i] = rsqrtf((float)(g_deg[i] + 1));  // +1 self loop
}

// ---------------- precompute: g_B1 = bf16(We2@Wc1c), g_B2 = bf16(Wc2),
//                  c1p = bc1 + be2@Wc1c ----------------
__global__ void k_prep(const float* __restrict__ We2, const float* __restrict__ Wc1,
                       const float* __restrict__ be2, const float* __restrict__ bc1,
                       const float* __restrict__ Wc2) {
    int idx = blockIdx.x*256 + threadIdx.x;   // 0..24575
    const float* Wc1c = Wc1 + 256*HD;
    if (idx < 16384) {
        int k = idx >> 7, n = idx & 127;
        float s = 0.f;
        for (int j = 0; j < HD; j++) s += __ldg(We2 + k*HD + j) * __ldg(Wc1c + j*HD + n);
        g_B1[idx] = __float2bfloat16(s);
        if (idx < 128) {
            float c = __ldg(bc1 + idx);
            for (int j = 0; j < HD; j++) c += __ldg(be2 + j) * __ldg(Wc1c + j*HD + idx);
            g_c1p[idx] = c;
        }
    } else {
        int t = idx - 16384;        // 0..8191
        g_B2[t] = __float2bfloat16(__ldg(Wc2 + t));
    }
}

// ---------------- layer-1 transform (K=8) ----------------
__global__ void k_transform1(const float* __restrict__ x, const float* __restrict__ W1,
                             float* __restrict__ tout, float* __restrict__ selfout) {
    __shared__ float sx[64*FNI];
    __shared__ float sw[FNI*HD];
    int j = threadIdx.x;  // 0..127
    for (int i = j; i < FNI*HD; i += 128) sw[i] = W1[i];
    int r0 = blockIdx.x * 64;
    for (int i = j; i < 64*FNI; i += 128) {
        int r = r0 + (i >> 3);
        sx[i] = (r < NN) ? x[r*FNI + (i & 7)] : 0.f;
    }
    __syncthreads();
    int mmax = min(64, NN - r0);
    for (int m = 0; m < mmax; m++) {
        int r = r0 + m;
        float acc = 0.f;
        #pragma unroll
        for (int k = 0; k < FNI; k++) acc += sx[m*FNI + k] * sw[k*HD + j];
        float d = g_dinv[r];
        tout[r*HD + j]    = acc;
        selfout[r*HD + j] = d*d*acc;
    }
}

// ---------------- node GEMM (K=128) ----------------
__global__ __launch_bounds__(256) void k_node_gemm(const float* __restrict__ A,
        const float* __restrict__ W, float* __restrict__ tout, float* __restrict__ selfout) {
    __shared__ float sA[64*HD];   // 32KB
    int tid = threadIdx.x, ty = tid >> 4, tx = tid & 15;
    int r0 = blockIdx.x * 64;
    float4* sA4 = (float4*)sA;
    float4 z4; z4.x = z4.y = z4.z = z4.w = 0.f;
    for (int i = tid; i < 64*32; i += 256) {
        int m = i >> 5, q = i & 31; int r = r0 + m;
        sA4[i] = (r < NN) ? __ldg(((const float4*)A) + (size_t)r*32 + q) : z4;
    }
    __syncthreads();
    float acc[4][8];
    #pragma unroll
    for (int i = 0; i < 4; i++)
        #pragma unroll
        for (int j = 0; j < 8; j++) acc[i][j] = 0.f;
    const float4* W4 = (const float4*)W;
    #pragma unroll 4
    for (int k = 0; k < HD; k++) {
        float a0 = sA[(ty*4+0)*HD + k];
        float a1 = sA[(ty*4+1)*HD + k];
        float a2 = sA[(ty*4+2)*HD + k];
        float a3 = sA[(ty*4+3)*HD + k];
        float4 b0 = __ldg(W4 + k*32 + tx*2);
        float4 b1 = __ldg(W4 + k*32 + tx*2 + 1);
        float bb[8] = {b0.x,b0.y,b0.z,b0.w,b1.x,b1.y,b1.z,b1.w};
        #pragma unroll
        for (int j = 0; j < 8; j++) {
            acc[0][j] += a0*bb[j];
            acc[1][j] += a1*bb[j];
            acc[2][j] += a2*bb[j];
            acc[3][j] += a3*bb[j];
        }
    }
    #pragma unroll
    for (int i = 0; i < 4; i++) {
        int r = r0 + ty*4 + i;
        if (r >= NN) break;
        float d = g_dinv[r]; float dd = d*d;
        size_t base = (size_t)r*HD + tx*8;
        #pragma unroll
        for (int j = 0; j < 8; j++) {
            float v = acc[i][j];
            tout[base + j] = v;
            if (selfout) selfout[base + j] = dd * v;
        }
    }
}

// ---------------- edge scatter ----------------
__global__ void k_scatter(const int* __restrict__ row, const int* __restrict__ col,
                          const float* __restrict__ t, float* __restrict__ out) {
    int gid = blockIdx.x*blockDim.x + threadIdx.x;
    int e = gid >> 5;
    if (e >= NE) return;
    int lane = gid & 31;
    int r = __ldg(row + e), c = __ldg(col + e);
    float w = g_dinv[r] * g_dinv[c];
    float4 v = __ldg(((const float4*)t) + (size_t)r*32 + lane);
    float* dst = out + (size_t)c*HD + lane*4;
    asm volatile("red.global.add.v4.f32 [%0], {%1,%2,%3,%4};"
                 :: "l"(dst), "f"(v.x*w), "f"(v.y*w), "f"(v.z*w), "f"(v.w*w) : "memory");
}

// ---------------- finalize: h = relu(h + b) ----------------
__global__ void k_finalize(float* __restrict__ h, const float* __restrict__ b) {
    int i = blockIdx.x*blockDim.x + threadIdx.x;
    if (i < NN*HD) {
        float v = h[i] + __ldg(b + (i & 127));
        h[i] = fmaxf(v, 0.f);
    }
}

// ---------------- fused edge MLP, mma.sync bf16 ----------------
// row strides (bf16 elems): A/B1 = 136, B2 = 72  (272B / 144B rows: 8-row
// ldmatrix spans all 32 banks -> conflict-free)
#define SAS 136
#define SBS 72
// smem byte offsets
#define O_SA    0          // 128 x 136 bf16 (a tile, then z1)
#define O_SB1   34816      // 128 x 136 bf16 (M, K-major)
#define O_SB2   69632      // 128 x 72  bf16 (Wc2, K-major)
#define O_SEA   88064      // 128x4 f32
#define O_SWE1  90112      // 4x128 f32
#define O_SBE1  92160      // 128 f32
#define O_SC1P  92672      // 128 f32
#define O_SWC3  93184      // 128 f32
#define O_SBC2  93696      // 64 f32
#define O_SIDX  93952      // 256 int
#define SMEM_EDGE_BYTES 94976

__global__ __launch_bounds__(256, 2) void k_edge_mlp(
        const int* __restrict__ row, const int* __restrict__ col,
        const float* __restrict__ ea,
        const float* __restrict__ We1, const float* __restrict__ be1,
        const float* __restrict__ bc2, const float* __restrict__ Wc3,
        const float* __restrict__ bc3,
        const float* __restrict__ U, const float* __restrict__ V,
        float* __restrict__ out) {
    extern __shared__ char smem[];
    uint32_t sbase = smem_u32(smem);
    int tid = threadIdx.x;
    int wid = tid >> 5, lane = tid & 31;
    int e0 = blockIdx.x * EB;

    float* sEA  = (float*)(smem + O_SEA);
    float* sWe1 = (float*)(smem + O_SWE1);
    float* sbe1 = (float*)(smem + O_SBE1);
    float* sC1p = (float*)(smem + O_SC1P);
    float* sWc3 = (float*)(smem + O_SWC3);
    float* sbc2 = (float*)(smem + O_SBC2);
    int*   sIdx = (int*)(smem + O_SIDX);
    uint32_t* sA1u = (uint32_t*)(smem + O_SA);
    uint32_t* sB1u = (uint32_t*)(smem + O_SB1);
    uint32_t* sB2u = (uint32_t*)(smem + O_SB2);

    // ---- loads ----
    if (tid < 128) {
        sIdx[tid]       = __ldg(row + e0 + tid);
        sIdx[128 + tid] = __ldg(col + e0 + tid);
        sbe1[tid] = __ldg(be1 + tid);
        sC1p[tid] = g_c1p[tid];
        sWc3[tid] = __ldg(Wc3 + tid);
        if (tid < 64) sbc2[tid] = __ldg(bc2 + tid);
    }
    for (int i = tid; i < 512; i += 256) {
        sEA[i]  = __ldg(ea + (size_t)e0*4 + i);
        sWe1[i] = __ldg(We1 + i);
    }
    // B1: [128][128] -> stride-136 smem (copy as bf16x2 words)
    {
        const uint32_t* src = (const uint32_t*)g_B1;
        for (int i = tid; i < 8192; i += 256) {
            int r = i >> 6, cp = i & 63;
            sB1u[r*(SAS/2) + cp] = __ldg(src + i);
        }
    }
    // B2: [128][64] -> stride-72 smem
    {
        const uint32_t* src = (const uint32_t*)g_B2;
        for (int i = tid; i < 4096; i += 256) {
            int r = i >> 5, cp = i & 31;
            sB2u[r*(SBS/2) + cp] = __ldg(src + i);
        }
    }
    __syncthreads();

    // ---- a = relu(ea@We1 + be1) -> bf16 sA ----
    for (int i = tid; i < 128*64; i += 256) {
        int m = i >> 6, kp = i & 63; int k = kp << 1;
        float ev0 = sEA[m*4+0], ev1 = sEA[m*4+1], ev2 = sEA[m*4+2], ev3 = sEA[m*4+3];
        float a0 = sbe1[k]   + ev0*sWe1[k]     + ev1*sWe1[128+k]   + ev2*sWe1[256+k]   + ev3*sWe1[384+k];
        float a1 = sbe1[k+1] + ev0*sWe1[k+1]   + ev1*sWe1[128+k+1] + ev2*sWe1[256+k+1] + ev3*sWe1[384+k+1];
        sA1u[m*(SAS/2) + kp] = pack_bf16x2(fmaxf(a0, 0.f), fmaxf(a1, 0.f));
    }
    __syncthreads();

    // ---- GEMM1: D[128,128] = a @ M ----
    int lr = lane & 15, lc = (lane >> 4) << 3;   // ldmatrix row / col-block
    float acc[16][4];
    #pragma unroll
    for (int i = 0; i < 16; i++)
        #pragma unroll
        for (int j = 0; j < 4; j++) acc[i][j] = 0.f;
    #pragma unroll
    for (int k0 = 0; k0 < 8; k0++) {
        uint32_t a[4];
        ldsm_x4(a, sbase + O_SA + ((16*wid + lr)*SAS + k0*16 + lc)*2);
        #pragma unroll
        for (int nt2 = 0; nt2 < 8; nt2++) {
            uint32_t b[4];
            ldsm_x4_t(b, sbase + O_SB1 + ((k0*16 + lr)*SAS + nt2*16 + lc)*2);
            mma_bf16(acc[2*nt2],     a, b[0], b[1]);
            mma_bf16(acc[2*nt2 + 1], a, b[2], b[3]);
        }
    }
    __syncthreads();   // all warps done reading sA (a tile)

    // ---- epilogue1: z1 = relu(D + U[row] + V[col] + c1p) -> bf16 sA ----
    {
        int r0 = 16*wid + (lane >> 2);       // rows r0, r0+8
        int q2 = (lane & 3) * 2;
        int rI0 = sIdx[r0],     cI0 = sIdx[128 + r0];
        int rI1 = sIdx[r0 + 8], cI1 = sIdx[128 + r0 + 8];
        const float* U0 = U + (size_t)rI0*HD;
        const float* V0 = V + (size_t)cI0*HD;
        const float* U1 = U + (size_t)rI1*HD;
        const float* V1 = V + (size_t)cI1*HD;
        #pragma unroll
        for (int nt = 0; nt < 16; nt++) {
            int c = nt*8 + q2;
            float2 u0 = *(const float2*)(U0 + c);
            float2 v0 = *(const float2*)(V0 + c);
            float2 u1 = *(const float2*)(U1 + c);
            float2 v1 = *(const float2*)(V1 + c);
            float p0 = sC1p[c], p1 = sC1p[c+1];
            float z0 = fmaxf(acc[nt][0] + u0.x + v0.x + p0, 0.f);
            float z1 = fmaxf(acc[nt][1] + u0.y + v0.y + p1, 0.f);
            float z2 = fmaxf(acc[nt][2] + u1.x + v1.x + p0, 0.f);
            float z3 = fmaxf(acc[nt][3] + u1.y + v1.y + p1, 0.f);
            sA1u[r0*(SAS/2) + (c >> 1)]       = pack_bf16x2(z0, z1);
            sA1u[(r0+8)*(SAS/2) + (c >> 1)]   = pack_bf16x2(z2, z3);
        }
    }
    __syncthreads();

    // ---- GEMM2: D2[128,64] = z1 @ Wc2 ----
    float acc2[8][4];
    #pragma unroll
    for (int i = 0; i < 8; i++)
        #pragma unroll
        for (int j = 0; j < 4; j++) acc2[i][j] = 0.f;
    #pragma unroll
    for (int k0 = 0; k0 < 8; k0++) {
        uint32_t a[4];
        ldsm_x4(a, sbase + O_SA + ((16*wid + lr)*SAS + k0*16 + lc)*2);
        #pragma unroll
        for (int nt2 = 0; nt2 < 4; nt2++) {
            uint32_t b[4];
            ldsm_x4_t(b, sbase + O_SB2 + ((k0*16 + lr)*SBS + nt2*16 + lc)*2);
            mma_bf16(acc2[2*nt2],     a, b[0], b[1]);
            mma_bf16(acc2[2*nt2 + 1], a, b[2], b[3]);
        }
    }

    // ---- epilogue2: z2 = relu(D2 + bc2); logits; log_softmax ----
    {
        int r0 = 16*wid + (lane >> 2);
        int q2 = (lane & 3) * 2;
        float l0a = 0.f, l1a = 0.f, l0b = 0.f, l1b = 0.f;
        #pragma unroll
        for (int nt = 0; nt < 8; nt++) {
            int c = nt*8 + q2;
            float b0 = sbc2[c], b1 = sbc2[c+1];
            float w00 = sWc3[2*c],     w01 = sWc3[2*c+1];
            float w10 = sWc3[2*c+2],   w11 = sWc3[2*c+3];
            float za = fmaxf(acc2[nt][0] + b0, 0.f);
            float zb = fmaxf(acc2[nt][1] + b1, 0.f);
            l0a += za*w00 + zb*w10;
            l1a += za*w01 + zb*w11;
            float zc = fmaxf(acc2[nt][2] + b0, 0.f);
            float zd = fmaxf(acc2[nt][3] + b1, 0.f);
            l0b += zc*w00 + zd*w10;
            l1b += zc*w01 + zd*w11;
        }
        #pragma unroll
        for (int off = 1; off <= 2; off <<= 1) {
            l0a += __shfl_xor_sync(0xFFFFFFFFu, l0a, off);
            l1a += __shfl_xor_sync(0xFFFFFFFFu, l1a, off);
            l0b += __shfl_xor_sync(0xFFFFFFFFu, l0b, off);
            l1b += __shfl_xor_sync(0xFFFFFFFFu, l1b, off);
        }
        if ((lane & 3) == 0) {
            float c3a = __ldg(bc3 + 0), c3b = __ldg(bc3 + 1);
            float L0 = l0a + c3a, L1 = l1a + c3b;
            float mx = fmaxf(L0, L1);
            float lse = mx + logf(expf(L0 - mx) + expf(L1 - mx));
            size_t o = (size_t)(e0 + r0) * 2;
            out[o + 0] = L0 - lse;
            out[o + 1] = L1 - lse;
            L0 = l0b + c3a; L1 = l1b + c3b;
            mx = fmaxf(L0, L1);
            lse = mx + logf(expf(L0 - mx) + expf(L1 - mx));
            o = (size_t)(e0 + r0 + 8) * 2;
            out[o + 0] = L0 - lse;
            out[o + 1] = L1 - lse;
        }
    }
}

// ---------------- launch ----------------
extern "C" void kernel_launch(void* const* d_in, const int* in_sizes, int n_in,
                              void* d_out, int out_size) {
    const float* x   = (const float*)d_in[0];
    const int*   ei  = (const int*)  d_in[1];
    const float* ea  = (const float*)d_in[2];
    const float* W1  = (const float*)d_in[3];
    const float* b1  = (const float*)d_in[4];
    const float* W2  = (const float*)d_in[5];
    const float* b2  = (const float*)d_in[6];
    const float* W3  = (const float*)d_in[7];
    const float* b3  = (const float*)d_in[8];
    const float* We1 = (const float*)d_in[9];
    const float* be1 = (const float*)d_in[10];
    const float* We2 = (const float*)d_in[11];
    const float* be2 = (const float*)d_in[12];
    const float* Wc1 = (const float*)d_in[13];
    const float* bc1 = (const float*)d_in[14];
    const float* Wc2 = (const float*)d_in[15];
    const float* bc2 = (const float*)d_in[16];
    const float* Wc3 = (const float*)d_in[17];
    const float* bc3 = (const float*)d_in[18];
    float* out = (float*)d_out;
    const int* row = ei;
    const int* col = ei + NE;

    float *h1, *h2, *t;
    cudaGetSymbolAddress((void**)&h1, g_h1);
    cudaGetSymbolAddress((void**)&h2, g_h2);
    cudaGetSymbolAddress((void**)&t,  g_t);

    k_deg_zero <<<(NN + 255)/256, 256>>>();
    k_deg_count<<<(NE + 255)/256, 256>>>(col);
    k_dinv     <<<(NN + 255)/256, 256>>>();
    k_prep     <<<96, 256>>>(We2, Wc1, be2, bc1, Wc2);

    // layer 1
    k_transform1<<<(NN + 63)/64, 128>>>(x, W1, t, h1);
    k_scatter   <<<(NE*32 + 255)/256, 256>>>(row, col, t, h1);
    k_finalize  <<<(NN*HD + 255)/256, 256>>>(h1, b1);
    // layer 2
    k_node_gemm <<<(NN + 63)/64, 256>>>(h1, W2, t, h2);
    k_scatter   <<<(NE*32 + 255)/256, 256>>>(row, col, t, h2);
    k_finalize  <<<(NN*HD + 255)/256, 256>>>(h2, b2);
    // layer 3
    k_node_gemm <<<(NN + 63)/64, 256>>>(h2, W3, t, h1);
    k_scatter   <<<(NE*32 + 255)/256, 256>>>(row, col, t, h1);
    k_finalize  <<<(NN*HD + 255)/256, 256>>>(h1, b3);

    // U = h@Wc1[0:128] -> t,  V = h@Wc1[128:256] -> h2
    k_node_gemm <<<(NN + 63)/64, 256>>>(h1, Wc1,         t,  nullptr);
    k_node_gemm <<<(NN + 63)/64, 256>>>(h1, Wc1 + HD*HD, h2, nullptr);

    cudaFuncSetAttribute(k_edge_mlp, cudaFuncAttributeMaxDynamicSharedMemorySize, SMEM_EDGE_BYTES);
    k_edge_mlp<<<NE/EB, 256, SMEM_EDGE_BYTES>>>(row, col, ea, We1, be1,
                                                bc2, Wc3, bc3, t, h2, out);
}

// round 5
// speedup vs baseline: 3.8269x; 1.9524x over previous
#include <cuda_runtime.h>
#include <cuda_bf16.h>
#include <math.h>
#include <stdint.h>

#define NN 50000
#define NE 800000
#define HD 128
#define FNI 8
#define FEI 4
#define EB 128   // edges per block in edge MLP

// ---------------- device scratch (no allocations allowed) ----------------
__device__ int   g_deg[NN];
__device__ int   g_off[NN+1];
__device__ int   g_cur[NN];
__device__ int   g_src[NE];
__device__ float g_dinv[NN];
__device__ float g_t[NN*HD];   // message buffer / U
__device__ float g_h1[NN*HD];  // h accumulator A
__device__ float g_h2[NN*HD];  // h accumulator B / V
__device__ float g_c1p[HD];    // bc1 + be2 @ Wc1[256:384]
__device__ __nv_bfloat16 g_B1[HD*HD];   // M = We2@Wc1c, row-major [k][n], bf16
__device__ __nv_bfloat16 g_B2[HD*64];   // Wc2 row-major [k][n], bf16
__device__ __nv_bfloat16 g_Wb2[HD*HD];  // bf16 W2
__device__ __nv_bfloat16 g_Wb3[HD*HD];  // bf16 W3
__device__ __nv_bfloat16 g_WbU[HD*HD];  // bf16 Wc1[0:128]
__device__ __nv_bfloat16 g_WbV[HD*HD];  // bf16 Wc1[128:256]

// ---------------- PTX helpers ----------------
__device__ __forceinline__ uint32_t smem_u32(const void* p) {
    uint32_t a;
    asm("{ .reg .u64 t; cvta.to.shared.u64 t, %1; cvt.u32.u64 %0, t; }" : "=r"(a) : "l"(p));
    return a;
}
__device__ __forceinline__ void ldsm_x4(uint32_t* r, uint32_t addr) {
    asm volatile("ldmatrix.sync.aligned.m8n8.x4.shared.b16 {%0,%1,%2,%3}, [%4];"
        : "=r"(r[0]), "=r"(r[1]), "=r"(r[2]), "=r"(r[3]) : "r"(addr));
}
__device__ __forceinline__ void ldsm_x4_t(uint32_t* r, uint32_t addr) {
    asm volatile("ldmatrix.sync.aligned.m8n8.x4.trans.shared.b16 {%0,%1,%2,%3}, [%4];"
        : "=r"(r[0]), "=r"(r[1]), "=r"(r[2]), "=r"(r[3]) : "r"(addr));
}
__device__ __forceinline__ void mma_bf16(float* d, const uint32_t* a, uint32_t b0, uint32_t b1) {
    asm volatile("mma.sync.aligned.m16n8k16.row.col.f32.bf16.bf16.f32 "
        "{%0,%1,%2,%3}, {%4,%5,%6,%7}, {%8,%9}, {%0,%1,%2,%3};"
        : "+f"(d[0]), "+f"(d[1]), "+f"(d[2]), "+f"(d[3])
        : "r"(a[0]), "r"(a[1]), "r"(a[2]), "r"(a[3]), "r"(b0), "r"(b1));
}
__device__ __forceinline__ uint32_t pack_bf16x2(float lo, float hi) {
    uint32_t p;
    asm("cvt.rn.bf16x2.f32 %0, %1, %2;" : "=r"(p) : "f"(hi), "f"(lo));
    return p;
}

// ---------------- degree / norm / CSR ----------------
__global__ void k_deg_zero() {
    int i = blockIdx.x*blockDim.x + threadIdx.x;
    if (i < NN) g_deg[i] = 0;
}
__global__ void k_deg_count(const int* __restrict__ col) {
    int i = blockIdx.x*blockDim.x + threadIdx.x;
    if (i < NE) atomicAdd(&g_deg[col[i]], 1);
}
__global__ void k_dinv() {
    int i = blockIdx.x*blockDim.x + threadIdx.x;
    if (i < NN) g_dinv[i] = rsqrtf((float)(g_deg[i] + 1));  // +1 self loop
}
// single-block exclusive scan of deg -> off, cur
__global__ void k_scan() {
    __shared__ int ws[32];
    __shared__ int s_tot;
    int tid = threadIdx.x, lane = tid & 31, wid = tid >> 5;
    int run = 0;
    for (int base = 0; base < NN; base += 1024) {
        int i = base + tid;
        int v = (i < NN) ? g_deg[i] : 0;
        int x = v;
        #pragma unroll
        for (int d = 1; d < 32; d <<= 1) {
            int y = __shfl_up_sync(0xFFFFFFFFu, x, d);
            if (lane >= d) x += y;
        }
        if (lane == 31) ws[wid] = x;
        __syncthreads();
        if (wid == 0) {
            int y = ws[lane];
            #pragma unroll
            for (int d = 1; d < 32; d <<= 1) {
                int z = __shfl_up_sync(0xFFFFFFFFu, y, d);
                if (lane >= d) y += z;
            }
            ws[lane] = y;
            if (lane == 31) s_tot = y;
        }
        __syncthreads();
        int excl = run + x - v + (wid > 0 ? ws[wid - 1] : 0);
        if (i < NN) { g_off[i] = excl; g_cur[i] = excl; }
        run += s_tot;
        __syncthreads();
    }
    if (tid == 0) g_off[NN] = run;
}
__global__ void k_fill(const int* __restrict__ row, const int* __restrict__ col) {
    int i = blockIdx.x*blockDim.x + threadIdx.x;
    if (i < NE) {
        int pos = atomicAdd(&g_cur[col[i]], 1);
        g_src[pos] = row[i];
    }
}

// ---------------- precompute: folded weights + bf16 weights ----------------
__global__ void k_prep(const float* __restrict__ We2, const float* __restrict__ Wc1,
                       const float* __restrict__ be2, const float* __restrict__ bc1,
                       const float* __restrict__ Wc2, const float* __restrict__ W2,
                       const float* __restrict__ W3) {
    int idx = blockIdx.x*256 + threadIdx.x;   // 0..90111
    const float* Wc1c = Wc1 + 256*HD;
    if (idx < 16384) {
        int k = idx >> 7, n = idx & 127;
        float s = 0.f;
        for (int j = 0; j < HD; j++) s += __ldg(We2 + k*HD + j) * __ldg(Wc1c + j*HD + n);
        g_B1[idx] = __float2bfloat16(s);
        if (idx < 128) {
            float c = __ldg(bc1 + idx);
            for (int j = 0; j < HD; j++) c += __ldg(be2 + j) * __ldg(Wc1c + j*HD + idx);
            g_c1p[idx] = c;
        }
    } else if (idx < 24576) {
        int t = idx - 16384;
        g_B2[t] = __float2bfloat16(__ldg(Wc2 + t));
    } else if (idx < 40960) {
        int t = idx - 24576;
        g_Wb2[t] = __float2bfloat16(__ldg(W2 + t));
    } else if (idx < 57344) {
        int t = idx - 40960;
        g_Wb3[t] = __float2bfloat16(__ldg(W3 + t));
    } else if (idx < 73728) {
        int t = idx - 57344;
        g_WbU[t] = __float2bfloat16(__ldg(Wc1 + t));
    } else if (idx < 90112) {
        int t = idx - 73728;
        g_WbV[t] = __float2bfloat16(__ldg(Wc1 + HD*HD + t));
    }
}

// ---------------- layer-1 transform (K=8): t_scaled = dinv * (x@W1) ----------------
__global__ void k_transform1(const float* __restrict__ x, const float* __restrict__ W1,
                             float* __restrict__ tout) {
    __shared__ float sx[64*FNI];
    __shared__ float sw[FNI*HD];
    int j = threadIdx.x;  // 0..127
    for (int i = j; i < FNI*HD; i += 128) sw[i] = W1[i];
    int r0 = blockIdx.x * 64;
    for (int i = j; i < 64*FNI; i += 128) {
        int r = r0 + (i >> 3);
        sx[i] = (r < NN) ? x[r*FNI + (i & 7)] : 0.f;
    }
    __syncthreads();
    int mmax = min(64, NN - r0);
    for (int m = 0; m < mmax; m++) {
        int r = r0 + m;
        float acc = 0.f;
        #pragma unroll
        for (int k = 0; k < FNI; k++) acc += sx[m*FNI + k] * sw[k*HD + j];
        tout[r*HD + j] = g_dinv[r] * acc;
    }
}

// ---------------- node GEMM via mma.sync bf16: out = (A @ Wb) [* dinv] ----------------
#define NSTR 136
#define O_NW 34816
#define SMEM_NODE_BYTES 69632

__global__ __launch_bounds__(256, 2) void k_node_mma(const float* __restrict__ A,
        const __nv_bfloat16* __restrict__ Wb, float* __restrict__ outp, int scaled) {
    extern __shared__ char smem[];
    uint32_t sbase = smem_u32(smem);
    uint32_t* sAu = (uint32_t*)smem;
    uint32_t* sWu = (uint32_t*)(smem + O_NW);
    int tid = threadIdx.x, wid = tid >> 5, lane = tid & 31;
    int r0 = blockIdx.x * 128;

    const uint32_t* wsrc = (const uint32_t*)Wb;
    for (int i = tid; i < 8192; i += 256) {
        int r = i >> 6, cp = i & 63;
        sWu[r*(NSTR/2) + cp] = __ldg(wsrc + i);
    }
    for (int i = tid; i < 8192; i += 256) {
        int m = i >> 6, kp = i & 63;
        int r = r0 + m; if (r >= NN) r = NN - 1;
        float2 v = __ldg((const float2*)(A + (size_t)r*HD) + kp);
        sAu[m*(NSTR/2) + kp] = pack_bf16x2(v.x, v.y);
    }
    __syncthreads();

    int lr = lane & 15, lc = (lane >> 4) << 3;
    float acc[16][4];
    #pragma unroll
    for (int i = 0; i < 16; i++)
        #pragma unroll
        for (int j = 0; j < 4; j++) acc[i][j] = 0.f;
    #pragma unroll
    for (int k0 = 0; k0 < 8; k0++) {
        uint32_t a[4];
        ldsm_x4(a, sbase + ((16*wid + lr)*NSTR + k0*16 + lc)*2);
        #pragma unroll
        for (int nt2 = 0; nt2 < 8; nt2++) {
            uint32_t b[4];
            ldsm_x4_t(b, sbase + O_NW + ((k0*16 + lr)*NSTR + nt2*16 + lc)*2);
            mma_bf16(acc[2*nt2],     a, b[0], b[1]);
            mma_bf16(acc[2*nt2 + 1], a, b[2], b[3]);
        }
    }

    int rA = r0 + 16*wid + (lane >> 2);
    int q2 = (lane & 3) * 2;
    if (rA < NN) {
        float s = scaled ? g_dinv[rA] : 1.f;
        #pragma unroll
        for (int nt = 0; nt < 16; nt++) {
            float2 st; st.x = acc[nt][0]*s; st.y = acc[nt][1]*s;
            *(float2*)(outp + (size_t)rA*HD + nt*8 + q2) = st;
        }
    }
    int rB = rA + 8;
    if (rB < NN) {
        float s = scaled ? g_dinv[rB] : 1.f;
        #pragma unroll
        for (int nt = 0; nt < 16; nt++) {
            float2 st; st.x = acc[nt][2]*s; st.y = acc[nt][3]*s;
            *(float2*)(outp + (size_t)rB*HD + nt*8 + q2) = st;
        }
    }
}

// ---------------- CSR gather-aggregate: h[c] = relu(dinv[c]*(sum msgs + self) + b) ----------------
__global__ __launch_bounds__(256) void k_aggregate(const float* __restrict__ t,
        const float* __restrict__ b, float* __restrict__ outp) {
    int wid = threadIdx.x >> 5, lane = threadIdx.x & 31;
    int c = blockIdx.x * 8 + wid;
    int start = __ldg(&g_off[c]), end = __ldg(&g_off[c+1]);
    const float4* tc = (const float4*)(t + (size_t)c*HD);
    float4 acc = __ldg(tc + lane);  // self term (t is pre-scaled by dinv[src])
    for (int base = start; base < end; base += 32) {
        int n = end - base;
        int myIdx = (lane < n) ? __ldg(&g_src[base + lane]) : 0;
        int cnt = min(32, n);
        for (int j = 0; j < cnt; j++) {
            int r = __shfl_sync(0xFFFFFFFFu, myIdx, j);
            float4 v = __ldg((const float4*)(t + (size_t)r*HD) + lane);
            acc.x += v.x; acc.y += v.y; acc.z += v.z; acc.w += v.w;
        }
    }
    float d = g_dinv[c];
    float4 bb = __ldg((const float4*)b + lane);
    float4 o;
    o.x = fmaxf(d*acc.x + bb.x, 0.f);
    o.y = fmaxf(d*acc.y + bb.y, 0.f);
    o.z = fmaxf(d*acc.z + bb.z, 0.f);
    o.w = fmaxf(d*acc.w + bb.w, 0.f);
    *((float4*)(outp + (size_t)c*HD) + lane) = o;
}

// ---------------- fused edge MLP, mma.sync bf16 ----------------
#define SAS 136
#define SBS 72
#define O_SA    0
#define O_SB1   34816
#define O_SB2   69632
#define O_SEA   88064
#define O_SWE1  90112
#define O_SBE1  92160
#define O_SC1P  92672
#define O_SWC3  93184
#define O_SBC2  93696
#define O_SIDX  93952
#define SMEM_EDGE_BYTES 94976

__global__ __launch_bounds__(256, 2) void k_edge_mlp(
        const int* __restrict__ row, const int* __restrict__ col,
        const float* __restrict__ ea,
        const float* __restrict__ We1, const float* __restrict__ be1,
        const float* __restrict__ bc2, const float* __restrict__ Wc3,
        const float* __restrict__ bc3,
        const float* __restrict__ U, const float* __restrict__ V,
        float* __restrict__ out) {
    extern __shared__ char smem[];
    uint32_t sbase = smem_u32(smem);
    int tid = threadIdx.x;
    int wid = tid >> 5, lane = tid & 31;
    int e0 = blockIdx.x * EB;

    float* sEA  = (float*)(smem + O_SEA);
    float* sWe1 = (float*)(smem + O_SWE1);
    float* sbe1 = (float*)(smem + O_SBE1);
    float* sC1p = (float*)(smem + O_SC1P);
    float* sWc3 = (float*)(smem + O_SWC3);
    float* sbc2 = (float*)(smem + O_SBC2);
    int*   sIdx = (int*)(smem + O_SIDX);
    uint32_t* sA1u = (uint32_t*)(smem + O_SA);
    uint32_t* sB1u = (uint32_t*)(smem + O_SB1);
    uint32_t* sB2u = (uint32_t*)(smem + O_SB2);

    if (tid < 128) {
        sIdx[tid]       = __ldg(row + e0 + tid);
        sIdx[128 + tid] = __ldg(col + e0 + tid);
        sbe1[tid] = __ldg(be1 + tid);
        sC1p[tid] = g_c1p[tid];
        sWc3[tid] = __ldg(Wc3 + tid);
        if (tid < 64) sbc2[tid] = __ldg(bc2 + tid);
    }
    for (int i = tid; i < 512; i += 256) {
        sEA[i]  = __ldg(ea + (size_t)e0*4 + i);
        sWe1[i] = __ldg(We1 + i);
    }
    {
        const uint32_t* src = (const uint32_t*)g_B1;
        for (int i = tid; i < 8192; i += 256) {
            int r = i >> 6, cp = i & 63;
            sB1u[r*(SAS/2) + cp] = __ldg(src + i);
        }
    }
    {
        const uint32_t* src = (const uint32_t*)g_B2;
        for (int i = tid; i < 4096; i += 256) {
            int r = i >> 5, cp = i & 31;
            sB2u[r*(SBS/2) + cp] = __ldg(src + i);
        }
    }
    __syncthreads();

    // a = relu(ea@We1 + be1) -> bf16 sA
    for (int i = tid; i < 128*64; i += 256) {
        int m = i >> 6, kp = i & 63; int k = kp << 1;
        float ev0 = sEA[m*4+0], ev1 = sEA[m*4+1], ev2 = sEA[m*4+2], ev3 = sEA[m*4+3];
        float a0 = sbe1[k]   + ev0*sWe1[k]     + ev1*sWe1[128+k]   + ev2*sWe1[256+k]   + ev3*sWe1[384+k];
        float a1 = sbe1[k+1] + ev0*sWe1[k+1]   + ev1*sWe1[128+k+1] + ev2*sWe1[256+k+1] + ev3*sWe1[384+k+1];
        sA1u[m*(SAS/2) + kp] = pack_bf16x2(fmaxf(a0, 0.f), fmaxf(a1, 0.f));
    }
    __syncthreads();

    // GEMM1: D[128,128] = a @ M
    int lr = lane & 15, lc = (lane >> 4) << 3;
    float acc[16][4];
    #pragma unroll
    for (int i = 0; i < 16; i++)
        #pragma unroll
        for (int j = 0; j < 4; j++) acc[i][j] = 0.f;
    #pragma unroll
    for (int k0 = 0; k0 < 8; k0++) {
        uint32_t a[4];
        ldsm_x4(a, sbase + O_SA + ((16*wid + lr)*SAS + k0*16 + lc)*2);
        #pragma unroll
        for (int nt2 = 0; nt2 < 8; nt2++) {
            uint32_t b[4];
            ldsm_x4_t(b, sbase + O_SB1 + ((k0*16 + lr)*SAS + nt2*16 + lc)*2);
            mma_bf16(acc[2*nt2],     a, b[0], b[1]);
            mma_bf16(acc[2*nt2 + 1], a, b[2], b[3]);
        }
    }
    __syncthreads();

    // epilogue1: z1 = relu(D + U[row] + V[col] + c1p) -> bf16 sA
    {
        int r0 = 16*wid + (lane >> 2);
        int q2 = (lane & 3) * 2;
        int rI0 = sIdx[r0],     cI0 = sIdx[128 + r0];
        int rI1 = sIdx[r0 + 8], cI1 = sIdx[128 + r0 + 8];
        const float* U0 = U + (size_t)rI0*HD;
        const float* V0 = V + (size_t)cI0*HD;
        const float* U1 = U + (size_t)rI1*HD;
        const float* V1 = V + (size_t)cI1*HD;
        #pragma unroll
        for (int nt = 0; nt < 16; nt++) {
            int c = nt*8 + q2;
            float2 u0 = *(const float2*)(U0 + c);
            float2 v0 = *(const float2*)(V0 + c);
            float2 u1 = *(const float2*)(U1 + c);
            float2 v1 = *(const float2*)(V1 + c);
            float p0 = sC1p[c], p1 = sC1p[c+1];
            float z0 = fmaxf(acc[nt][0] + u0.x + v0.x + p0, 0.f);
            float z1 = fmaxf(acc[nt][1] + u0.y + v0.y + p1, 0.f);
            float z2 = fmaxf(acc[nt][2] + u1.x + v1.x + p0, 0.f);
            float z3 = fmaxf(acc[nt][3] + u1.y + v1.y + p1, 0.f);
            sA1u[r0*(SAS/2) + (c >> 1)]       = pack_bf16x2(z0, z1);
            sA1u[(r0+8)*(SAS/2) + (c >> 1)]   = pack_bf16x2(z2, z3);
        }
    }
    __syncthreads();

    // GEMM2: D2[128,64] = z1 @ Wc2
    float acc2[8][4];
    #pragma unroll
    for (int i = 0; i < 8; i++)
        #pragma unroll
        for (int j = 0; j < 4; j++) acc2[i][j] = 0.f;
    #pragma unroll
    for (int k0 = 0; k0 < 8; k0++) {
        uint32_t a[4];
        ldsm_x4(a, sbase + O_SA + ((16*wid + lr)*SAS + k0*16 + lc)*2);
        #pragma unroll
        for (int nt2 = 0; nt2 < 4; nt2++) {
            uint32_t b[4];
            ldsm_x4_t(b, sbase + O_SB2 + ((k0*16 + lr)*SBS + nt2*16 + lc)*2);
            mma_bf16(acc2[2*nt2],     a, b[0], b[1]);
            mma_bf16(acc2[2*nt2 + 1], a, b[2], b[3]);
        }
    }

    // epilogue2: z2 = relu(D2 + bc2); logits; log_softmax
    {
        int r0 = 16*wid + (lane >> 2);
        int q2 = (lane & 3) * 2;
        float l0a = 0.f, l1a = 0.f, l0b = 0.f, l1b = 0.f;
        #pragma unroll
        for (int nt = 0; nt < 8; nt++) {
            int c = nt*8 + q2;
            float b0 = sbc2[c], b1 = sbc2[c+1];
            float w00 = sWc3[2*c],     w01 = sWc3[2*c+1];
            float w10 = sWc3[2*c+2],   w11 = sWc3[2*c+3];
            float za = fmaxf(acc2[nt][0] + b0, 0.f);
            float zb = fmaxf(acc2[nt][1] + b1, 0.f);
            l0a += za*w00 + zb*w10;
            l1a += za*w01 + zb*w11;
            float zc = fmaxf(acc2[nt][2] + b0, 0.f);
            float zd = fmaxf(acc2[nt][3] + b1, 0.f);
            l0b += zc*w00 + zd*w10;
            l1b += zc*w01 + zd*w11;
        }
        #pragma unroll
        for (int off = 1; off <= 2; off <<= 1) {
            l0a += __shfl_xor_sync(0xFFFFFFFFu, l0a, off);
            l1a += __shfl_xor_sync(0xFFFFFFFFu, l1a, off);
            l0b += __shfl_xor_sync(0xFFFFFFFFu, l0b, off);
            l1b += __shfl_xor_sync(0xFFFFFFFFu, l1b, off);
        }
        if ((lane & 3) == 0) {
            float c3a = __ldg(bc3 + 0), c3b = __ldg(bc3 + 1);
            float L0 = l0a + c3a, L1 = l1a + c3b;
            float mx = fmaxf(L0, L1);
            float lse = mx + logf(expf(L0 - mx) + expf(L1 - mx));
            size_t o = (size_t)(e0 + r0) * 2;
            out[o + 0] = L0 - lse;
            out[o + 1] = L1 - lse;
            L0 = l0b + c3a; L1 = l1b + c3b;
            mx = fmaxf(L0, L1);
            lse = mx + logf(expf(L0 - mx) + expf(L1 - mx));
            o = (size_t)(e0 + r0 + 8) * 2;
            out[o + 0] = L0 - lse;
            out[o + 1] = L1 - lse;
        }
    }
}

// ---------------- launch ----------------
extern "C" void kernel_launch(void* const* d_in, const int* in_sizes, int n_in,
                              void* d_out, int out_size) {
    const float* x   = (const float*)d_in[0];
    const int*   ei  = (const int*)  d_in[1];
    const float* ea  = (const float*)d_in[2];
    const float* W1  = (const float*)d_in[3];
    const float* b1  = (const float*)d_in[4];
    const float* W2  = (const float*)d_in[5];
    const float* b2  = (const float*)d_in[6];
    const float* W3  = (const float*)d_in[7];
    const float* b3  = (const float*)d_in[8];
    const float* We1 = (const float*)d_in[9];
    const float* be1 = (const float*)d_in[10];
    const float* We2 = (const float*)d_in[11];
    const float* be2 = (const float*)d_in[12];
    const float* Wc1 = (const float*)d_in[13];
    const float* bc1 = (const float*)d_in[14];
    const float* Wc2 = (const float*)d_in[15];
    const float* bc2 = (const float*)d_in[16];
    const float* Wc3 = (const float*)d_in[17];
    const float* bc3 = (const float*)d_in[18];
    float* out = (float*)d_out;
    const int* row = ei;
    const int* col = ei + NE;

    float *h1, *h2, *t;
    cudaGetSymbolAddress((void**)&h1, g_h1);
    cudaGetSymbolAddress((void**)&h2, g_h2);
    cudaGetSymbolAddress((void**)&t,  g_t);
    __nv_bfloat16 *wb2, *wb3, *wbu, *wbv;
    cudaGetSymbolAddress((void**)&wb2, g_Wb2);
    cudaGetSymbolAddress((void**)&wb3, g_Wb3);
    cudaGetSymbolAddress((void**)&wbu, g_WbU);
    cudaGetSymbolAddress((void**)&wbv, g_WbV);

    static int attr_set = 0;
    cudaFuncSetAttribute(k_node_mma, cudaFuncAttributeMaxDynamicSharedMemorySize, SMEM_NODE_BYTES);
    cudaFuncSetAttribute(k_edge_mlp, cudaFuncAttributeMaxDynamicSharedMemorySize, SMEM_EDGE_BYTES);
    (void)attr_set;

    // graph preprocessing
    k_deg_zero <<<(NN + 255)/256, 256>>>();
    k_deg_count<<<(NE + 255)/256, 256>>>(col);
    k_dinv     <<<(NN + 255)/256, 256>>>();
    k_scan     <<<1, 1024>>>();
    k_fill     <<<(NE + 255)/256, 256>>>(row, col);
    k_prep     <<<352, 256>>>(We2, Wc1, be2, bc1, Wc2, W2, W3);

    const int NB = (NN + 127)/128;
    // layer 1
    k_transform1<<<(NN + 63)/64, 128>>>(x, W1, t);
    k_aggregate <<<NN/8, 256>>>(t, b1, h1);
    // layer 2
    k_node_mma  <<<NB, 256, SMEM_NODE_BYTES>>>(h1, wb2, t, 1);
    k_aggregate <<<NN/8, 256>>>(t, b2, h2);
    // layer 3
    k_node_mma  <<<NB, 256, SMEM_NODE_BYTES>>>(h2, wb3, t, 1);
    k_aggregate <<<NN/8, 256>>>(t, b3, h1);

    // U = h@Wc1[0:128] -> t,  V = h@Wc1[128:256] -> h2
    k_node_mma  <<<NB, 256, SMEM_NODE_BYTES>>>(h1, wbu, t,  0);
    k_node_mma  <<<NB, 256, SMEM_NODE_BYTES>>>(h1, wbv, h2, 0);

    k_edge_mlp<<<NE/EB, 256, SMEM_EDGE_BYTES>>>(row, col, ea, We1, be1,
                                                bc2, Wc3, bc3, t, h2, out);
}

// round 6
// speedup vs baseline: 4.0565x; 1.0600x over previous
#include <cuda_runtime.h>
#include <cuda_bf16.h>
#include <math.h>
#include <stdint.h>

#define NN 50000
#define NE 800000
#define HD 128
#define FNI 8
#define FEI 4
#define EB 128   // edges per block in edge MLP
#define NCHUNK 49  // ceil(NN/1024)

// ---------------- device scratch (no allocations allowed) ----------------
__device__ int   g_deg[NN];
__device__ int   g_off[NN+1];
__device__ int   g_cur[NN];
__device__ int   g_src[NE];
__device__ int   g_bsum[NCHUNK];
__device__ float g_dinv[NN];
__device__ float g_t[NN*HD];   // U buffer (fp32)
__device__ float g_h1[NN*HD];  // h accumulator A
__device__ float g_h2[NN*HD];  // h accumulator B / V
__device__ __nv_bfloat16 g_tb[NN*HD];   // bf16 message buffer
__device__ float g_c1p[HD];    // bc1 + be2 @ Wc1[256:384]
__device__ __nv_bfloat16 g_B1[HD*HD];   // M = We2@Wc1c, row-major [k][n], bf16
__device__ __nv_bfloat16 g_B2[HD*64];   // Wc2 row-major [k][n], bf16
__device__ __nv_bfloat16 g_Wb2[HD*HD];  // bf16 W2
__device__ __nv_bfloat16 g_Wb3[HD*HD];  // bf16 W3
__device__ __nv_bfloat16 g_WbU[HD*HD];  // bf16 Wc1[0:128]
__device__ __nv_bfloat16 g_WbV[HD*HD];  // bf16 Wc1[128:256]

// ---------------- PTX helpers ----------------
__device__ __forceinline__ uint32_t smem_u32(const void* p) {
    uint32_t a;
    asm("{ .reg .u64 t; cvta.to.shared.u64 t, %1; cvt.u32.u64 %0, t; }" : "=r"(a) : "l"(p));
    return a;
}
__device__ __forceinline__ void ldsm_x4(uint32_t* r, uint32_t addr) {
    asm volatile("ldmatrix.sync.aligned.m8n8.x4.shared.b16 {%0,%1,%2,%3}, [%4];"
        : "=r"(r[0]), "=r"(r[1]), "=r"(r[2]), "=r"(r[3]) : "r"(addr));
}
__device__ __forceinline__ void ldsm_x4_t(uint32_t* r, uint32_t addr) {
    asm volatile("ldmatrix.sync.aligned.m8n8.x4.trans.shared.b16 {%0,%1,%2,%3}, [%4];"
        : "=r"(r[0]), "=r"(r[1]), "=r"(r[2]), "=r"(r[3]) : "r"(addr));
}
__device__ __forceinline__ void mma_bf16(float* d, const uint32_t* a, uint32_t b0, uint32_t b1) {
    asm volatile("mma.sync.aligned.m16n8k16.row.col.f32.bf16.bf16.f32 "
        "{%0,%1,%2,%3}, {%4,%5,%6,%7}, {%8,%9}, {%0,%1,%2,%3};"
        : "+f"(d[0]), "+f"(d[1]), "+f"(d[2]), "+f"(d[3])
        : "r"(a[0]), "r"(a[1]), "r"(a[2]), "r"(a[3]), "r"(b0), "r"(b1));
}
__device__ __forceinline__ uint32_t pack_bf16x2(float lo, float hi) {
    uint32_t p;
    asm("cvt.rn.bf16x2.f32 %0, %1, %2;" : "=r"(p) : "f"(hi), "f"(lo));
    return p;
}

// ---------------- degree / norm / CSR ----------------
__global__ void k_deg_zero() {
    int i = blockIdx.x*blockDim.x + threadIdx.x;
    if (i < NN) g_deg[i] = 0;
}
__global__ void k_deg_count(const int* __restrict__ col) {
    int i = blockIdx.x*blockDim.x + threadIdx.x;
    if (i < NE) atomicAdd(&g_deg[col[i]], 1);
}
// phase A: per-chunk exclusive scan (+dinv)
__global__ __launch_bounds__(1024) void k_scanA() {
    __shared__ int ws[32];
    int tid = threadIdx.x, lane = tid & 31, w = tid >> 5;
    int i = blockIdx.x*1024 + tid;
    int v = (i < NN) ? g_deg[i] : 0;
    if (i < NN) g_dinv[i] = rsqrtf((float)(v + 1));  // +1 self loop
    int x = v;
    #pragma unroll
    for (int d = 1; d < 32; d <<= 1) {
        int y = __shfl_up_sync(0xFFFFFFFFu, x, d);
        if (lane >= d) x += y;
    }
    if (lane == 31) ws[w] = x;
    __syncthreads();
    if (w == 0) {
        int y = ws[lane];
        #pragma unroll
        for (int d = 1; d < 32; d <<= 1) {
            int z = __shfl_up_sync(0xFFFFFFFFu, y, d);
            if (lane >= d) y += z;
        }
        ws[lane] = y;
    }
    __syncthreads();
    int excl = x - v + (w > 0 ? ws[w-1] : 0);
    if (i < NN) g_off[i] = excl;
    if (tid == 1023) g_bsum[blockIdx.x] = ws[31];
}
// phase B: scan the chunk sums (1 block, 64 threads)
__global__ void k_scanB() {
    __shared__ int wtot[2];
    int tid = threadIdx.x, lane = tid & 31, w = tid >> 5;
    int v = (tid < NCHUNK) ? g_bsum[tid] : 0;
    int x = v;
    #pragma unroll
    for (int d = 1; d < 32; d <<= 1) {
        int y = __shfl_up_sync(0xFFFFFFFFu, x, d);
        if (lane >= d) x += y;
    }
    if (lane == 31) wtot[w] = x;
    __syncthreads();
    if (w == 1) x += wtot[0];
    if (tid < NCHUNK) g_bsum[tid] = x - v;   // exclusive base
    if (tid == 0) g_off[NN] = wtot[0] + wtot[1];
}
// phase C: add chunk base, init cursors
__global__ void k_scanC() {
    int i = blockIdx.x*blockDim.x + threadIdx.x;
    if (i < NN) {
        int o = g_off[i] + g_bsum[i >> 10];
        g_off[i] = o;
        g_cur[i] = o;
    }
}
__global__ void k_fill(const int* __restrict__ row, const int* __restrict__ col) {
    int i = blockIdx.x*blockDim.x + threadIdx.x;
    if (i < NE) {
        int pos = atomicAdd(&g_cur[col[i]], 1);
        g_src[pos] = row[i];
    }
}

// ---------------- precompute: folded weights + bf16 weights ----------------
__global__ void k_prep(const float* __restrict__ We2, const float* __restrict__ Wc1,
                       const float* __restrict__ be2, const float* __restrict__ bc1,
                       const float* __restrict__ Wc2, const float* __restrict__ W2,
                       const float* __restrict__ W3) {
    int idx = blockIdx.x*256 + threadIdx.x;   // 0..90111
    const float* Wc1c = Wc1 + 256*HD;
    if (idx < 16384) {
        int k = idx >> 7, n = idx & 127;
        float s = 0.f;
        for (int j = 0; j < HD; j++) s += __ldg(We2 + k*HD + j) * __ldg(Wc1c + j*HD + n);
        g_B1[idx] = __float2bfloat16(s);
        if (idx < 128) {
            float c = __ldg(bc1 + idx);
            for (int j = 0; j < HD; j++) c += __ldg(be2 + j) * __ldg(Wc1c + j*HD + idx);
            g_c1p[idx] = c;
        }
    } else if (idx < 24576) {
        int t = idx - 16384;
        g_B2[t] = __float2bfloat16(__ldg(Wc2 + t));
    } else if (idx < 40960) {
        int t = idx - 24576;
        g_Wb2[t] = __float2bfloat16(__ldg(W2 + t));
    } else if (idx < 57344) {
        int t = idx - 40960;
        g_Wb3[t] = __float2bfloat16(__ldg(W3 + t));
    } else if (idx < 73728) {
        int t = idx - 57344;
        g_WbU[t] = __float2bfloat16(__ldg(Wc1 + t));
    } else if (idx < 90112) {
        int t = idx - 73728;
        g_WbV[t] = __float2bfloat16(__ldg(Wc1 + HD*HD + t));
    }
}

// ---------------- layer-1 transform (K=8): tb = bf16(dinv * (x@W1)) ----------------
__global__ void k_transform1(const float* __restrict__ x, const float* __restrict__ W1,
                             __nv_bfloat16* __restrict__ tout) {
    __shared__ float sx[64*FNI];
    __shared__ float sw[FNI*HD];
    int tid = threadIdx.x;  // 0..127
    for (int i = tid; i < FNI*HD; i += 128) sw[i] = W1[i];
    int r0 = blockIdx.x * 64;
    for (int i = tid; i < 64*FNI; i += 128) {
        int r = r0 + (i >> 3);
        sx[i] = (r < NN) ? x[r*FNI + (i & 7)] : 0.f;
    }
    __syncthreads();
    int c = (tid & 63) * 2;
    int half = tid >> 6;
    for (int m = half*32; m < half*32 + 32; m++) {
        int r = r0 + m;
        if (r >= NN) break;
        float a0 = 0.f, a1 = 0.f;
        #pragma unroll
        for (int k = 0; k < FNI; k++) {
            float xv = sx[m*FNI + k];
            a0 += xv * sw[k*HD + c];
            a1 += xv * sw[k*HD + c + 1];
        }
        float d = g_dinv[r];
        ((uint32_t*)tout)[(size_t)r*64 + (c >> 1)] = pack_bf16x2(d*a0, d*a1);
    }
}

// ---------------- node GEMM via mma.sync bf16 ----------------
// outb != null : out = bf16(dinv * (A@Wb))  (message path)
// outb == null : outf = fp32(A@Wb)          (U/V path)
#define NSTR 136
#define O_NW 34816
#define SMEM_NODE_BYTES 69632

__global__ __launch_bounds__(256, 2) void k_node_mma(const float* __restrict__ A,
        const __nv_bfloat16* __restrict__ Wb,
        __nv_bfloat16* __restrict__ outb, float* __restrict__ outf) {
    extern __shared__ char smem[];
    uint32_t sbase = smem_u32(smem);
    uint32_t* sAu = (uint32_t*)smem;
    uint32_t* sWu = (uint32_t*)(smem + O_NW);
    int tid = threadIdx.x, wid = tid >> 5, lane = tid & 31;
    int r0 = blockIdx.x * 128;

    const uint32_t* wsrc = (const uint32_t*)Wb;
    for (int i = tid; i < 8192; i += 256) {
        int r = i >> 6, cp = i & 63;
        sWu[r*(NSTR/2) + cp] = __ldg(wsrc + i);
    }
    for (int i = tid; i < 8192; i += 256) {
        int m = i >> 6, kp = i & 63;
        int r = r0 + m; if (r >= NN) r = NN - 1;
        float2 v = __ldg((const float2*)(A + (size_t)r*HD) + kp);
        sAu[m*(NSTR/2) + kp] = pack_bf16x2(v.x, v.y);
    }
    __syncthreads();

    int lr = lane & 15, lc = (lane >> 4) << 3;
    float acc[16][4];
    #pragma unroll
    for (int i = 0; i < 16; i++)
        #pragma unroll
        for (int j = 0; j < 4; j++) acc[i][j] = 0.f;
    #pragma unroll
    for (int k0 = 0; k0 < 8; k0++) {
        uint32_t a[4];
        ldsm_x4(a, sbase + ((16*wid + lr)*NSTR + k0*16 + lc)*2);
        #pragma unroll
        for (int nt2 = 0; nt2 < 8; nt2++) {
            uint32_t b[4];
            ldsm_x4_t(b, sbase + O_NW + ((k0*16 + lr)*NSTR + nt2*16 + lc)*2);
            mma_bf16(acc[2*nt2],     a, b[0], b[1]);
            mma_bf16(acc[2*nt2 + 1], a, b[2], b[3]);
        }
    }

    int rA = r0 + 16*wid + (lane >> 2);
    int rB = rA + 8;
    int q = lane & 3;
    if (outb) {
        if (rA < NN) {
            float s = g_dinv[rA];
            uint32_t* ob = (uint32_t*)outb + (size_t)rA*64;
            #pragma unroll
            for (int nt = 0; nt < 16; nt++)
                ob[nt*4 + q] = pack_bf16x2(acc[nt][0]*s, acc[nt][1]*s);
        }
        if (rB < NN) {
            float s = g_dinv[rB];
            uint32_t* ob = (uint32_t*)outb + (size_t)rB*64;
            #pragma unroll
            for (int nt = 0; nt < 16; nt++)
                ob[nt*4 + q] = pack_bf16x2(acc[nt][2]*s, acc[nt][3]*s);
        }
    } else {
        if (rA < NN) {
            #pragma unroll
            for (int nt = 0; nt < 16; nt++) {
                float2 st; st.x = acc[nt][0]; st.y = acc[nt][1];
                *(float2*)(outf + (size_t)rA*HD + nt*8 + q*2) = st;
            }
        }
        if (rB < NN) {
            #pragma unroll
            for (int nt = 0; nt < 16; nt++) {
                float2 st; st.x = acc[nt][2]; st.y = acc[nt][3];
                *(float2*)(outf + (size_t)rB*HD + nt*8 + q*2) = st;
            }
        }
    }
}

// ---------------- CSR gather-aggregate (bf16 messages) ----------------
// h[c] = relu(dinv[c]*(sum_{r in N(c)} tb[r] + tb[c]) + b)
__device__ __forceinline__ void acc_bf16x2(uint32_t u, float& lo, float& hi) {
    lo += __uint_as_float(u << 16);
    hi += __uint_as_float(u & 0xFFFF0000u);
}
__global__ __launch_bounds__(256) void k_aggregate(const __nv_bfloat16* __restrict__ t,
        const float* __restrict__ b, float* __restrict__ outp) {
    int wid = threadIdx.x >> 5, lane = threadIdx.x & 31;
    int c = blockIdx.x * 8 + wid;
    int start = __ldg(&g_off[c]), end = __ldg(&g_off[c+1]);
    const uint2* T = (const uint2*)t;   // 32 uint2 per row (128 bf16)
    float ax = 0.f, ay = 0.f, az = 0.f, aw = 0.f;
    {   // self term
        uint2 sv = __ldg(T + (size_t)c*32 + lane);
        acc_bf16x2(sv.x, ax, ay);
        acc_bf16x2(sv.y, az, aw);
    }
    for (int base = start; base < end; base += 32) {
        int n = end - base;
        int myIdx = (lane < n) ? __ldg(&g_src[base + lane]) : 0;
        int cnt = min(32, n);
        for (int j = 0; j < cnt; j++) {
            int r = __shfl_sync(0xFFFFFFFFu, myIdx, j);
            uint2 v = __ldg(T + (size_t)r*32 + lane);
            acc_bf16x2(v.x, ax, ay);
            acc_bf16x2(v.y, az, aw);
        }
    }
    float d = g_dinv[c];
    float4 bb = __ldg((const float4*)b + lane);
    float4 o;
    o.x = fmaxf(d*ax + bb.x, 0.f);
    o.y = fmaxf(d*ay + bb.y, 0.f);
    o.z = fmaxf(d*az + bb.z, 0.f);
    o.w = fmaxf(d*aw + bb.w, 0.f);
    *((float4*)(outp + (size_t)c*HD) + lane) = o;
}

// ---------------- fused edge MLP, mma.sync bf16 ----------------
#define SAS 136
#define SBS 72
#define O_SA    0
#define O_SB1   34816
#define O_SB2   69632
#define O_SEA   88064
#define O_SWE1  90112
#define O_SBE1  92160
#define O_SC1P  92672
#define O_SWC3  93184
#define O_SBC2  93696
#define O_SIDX  93952
#define SMEM_EDGE_BYTES 94976

__global__ __launch_bounds__(256, 2) void k_edge_mlp(
        const int* __restrict__ row, const int* __restrict__ col,
        const float* __restrict__ ea,
        const float* __restrict__ We1, const float* __restrict__ be1,
        const float* __restrict__ bc2, const float* __restrict__ Wc3,
        const float* __restrict__ bc3,
        const float* __restrict__ U, const float* __restrict__ V,
        float* __restrict__ out) {
    extern __shared__ char smem[];
    uint32_t sbase = smem_u32(smem);
    int tid = threadIdx.x;
    int wid = tid >> 5, lane = tid & 31;
    int e0 = blockIdx.x * EB;

    float* sEA  = (float*)(smem + O_SEA);
    float* sWe1 = (float*)(smem + O_SWE1);
    float* sbe1 = (float*)(smem + O_SBE1);
    float* sC1p = (float*)(smem + O_SC1P);
    float* sWc3 = (float*)(smem + O_SWC3);
    float* sbc2 = (float*)(smem + O_SBC2);
    int*   sIdx = (int*)(smem + O_SIDX);
    uint32_t* sA1u = (uint32_t*)(smem + O_SA);
    uint32_t* sB1u = (uint32_t*)(smem + O_SB1);
    uint32_t* sB2u = (uint32_t*)(smem + O_SB2);

    if (tid < 128) {
        sIdx[tid]       = __ldg(row + e0 + tid);
        sIdx[128 + tid] = __ldg(col + e0 + tid);
        sbe1[tid] = __ldg(be1 + tid);
        sC1p[tid] = g_c1p[tid];
        sWc3[tid] = __ldg(Wc3 + tid);
        if (tid < 64) sbc2[tid] = __ldg(bc2 + tid);
    }
    for (int i = tid; i < 512; i += 256) {
        sEA[i]  = __ldg(ea + (size_t)e0*4 + i);
        sWe1[i] = __ldg(We1 + i);
    }
    {
        const uint32_t* src = (const uint32_t*)g_B1;
        for (int i = tid; i < 8192; i += 256) {
            int r = i >> 6, cp = i & 63;
            sB1u[r*(SAS/2) + cp] = __ldg(src + i);
        }
    }
    {
        const uint32_t* src = (const uint32_t*)g_B2;
        for (int i = tid; i < 4096; i += 256) {
            int r = i >> 5, cp = i & 31;
            sB2u[r*(SBS/2) + cp] = __ldg(src + i);
        }
    }
    __syncthreads();

    // a = relu(ea@We1 + be1) -> bf16 sA
    for (int i = tid; i < 128*64; i += 256) {
        int m = i >> 6, kp = i & 63; int k = kp << 1;
        float ev0 = sEA[m*4+0], ev1 = sEA[m*4+1], ev2 = sEA[m*4+2], ev3 = sEA[m*4+3];
        float a0 = sbe1[k]   + ev0*sWe1[k]     + ev1*sWe1[128+k]   + ev2*sWe1[256+k]   + ev3*sWe1[384+k];
        float a1 = sbe1[k+1] + ev0*sWe1[k+1]   + ev1*sWe1[128+k+1] + ev2*sWe1[256+k+1] + ev3*sWe1[384+k+1];
        sA1u[m*(SAS/2) + kp] = pack_bf16x2(fmaxf(a0, 0.f), fmaxf(a1, 0.f));
    }
    __syncthreads();

    // GEMM1: D[128,128] = a @ M
    int lr = lane & 15, lc = (lane >> 4) << 3;
    float acc[16][4];
    #pragma unroll
    for (int i = 0; i < 16; i++)
        #pragma unroll
        for (int j = 0; j < 4; j++) acc[i][j] = 0.f;
    #pragma unroll
    for (int k0 = 0; k0 < 8; k0++) {
        uint32_t a[4];
        ldsm_x4(a, sbase + O_SA + ((16*wid + lr)*SAS + k0*16 + lc)*2);
        #pragma unroll
        for (int nt2 = 0; nt2 < 8; nt2++) {
            uint32_t b[4];
            ldsm_x4_t(b, sbase + O_SB1 + ((k0*16 + lr)*SAS + nt2*16 + lc)*2);
            mma_bf16(acc[2*nt2],     a, b[0], b[1]);
            mma_bf16(acc[2*nt2 + 1], a, b[2], b[3]);
        }
    }
    __syncthreads();

    // epilogue1: z1 = relu(D + U[row] + V[col] + c1p) -> bf16 sA
    {
        int r0 = 16*wid + (lane >> 2);
        int q2 = (lane & 3) * 2;
        int rI0 = sIdx[r0],     cI0 = sIdx[128 + r0];
        int rI1 = sIdx[r0 + 8], cI1 = sIdx[128 + r0 + 8];
        const float* U0 = U + (size_t)rI0*HD;
        const float* V0 = V + (size_t)cI0*HD;
        const float* U1 = U + (size_t)rI1*HD;
        const float* V1 = V + (size_t)cI1*HD;
        #pragma unroll
        for (int nt = 0; nt < 16; nt++) {
            int c = nt*8 + q2;
            float2 u0 = *(const float2*)(U0 + c);
            float2 v0 = *(const float2*)(V0 + c);
            float2 u1 = *(const float2*)(U1 + c);
            float2 v1 = *(const float2*)(V1 + c);
            float p0 = sC1p[c], p1 = sC1p[c+1];
            float z0 = fmaxf(acc[nt][0] + u0.x + v0.x + p0, 0.f);
            float z1 = fmaxf(acc[nt][1] + u0.y + v0.y + p1, 0.f);
            float z2 = fmaxf(acc[nt][2] + u1.x + v1.x + p0, 0.f);
            float z3 = fmaxf(acc[nt][3] + u1.y + v1.y + p1, 0.f);
            sA1u[r0*(SAS/2) + (c >> 1)]       = pack_bf16x2(z0, z1);
            sA1u[(r0+8)*(SAS/2) + (c >> 1)]   = pack_bf16x2(z2, z3);
        }
    }
    __syncthreads();

    // GEMM2: D2[128,64] = z1 @ Wc2
    float acc2[8][4];
    #pragma unroll
    for (int i = 0; i < 8; i++)
        #pragma unroll
        for (int j = 0; j < 4; j++) acc2[i][j] = 0.f;
    #pragma unroll
    for (int k0 = 0; k0 < 8; k0++) {
        uint32_t a[4];
        ldsm_x4(a, sbase + O_SA + ((16*wid + lr)*SAS + k0*16 + lc)*2);
        #pragma unroll
        for (int nt2 = 0; nt2 < 4; nt2++) {
            uint32_t b[4];
            ldsm_x4_t(b, sbase + O_SB2 + ((k0*16 + lr)*SBS + nt2*16 + lc)*2);
            mma_bf16(acc2[2*nt2],     a, b[0], b[1]);
            mma_bf16(acc2[2*nt2 + 1], a, b[2], b[3]);
        }
    }

    // epilogue2: z2 = relu(D2 + bc2); logits; log_softmax
    {
        int r0 = 16*wid + (lane >> 2);
        int q2 = (lane & 3) * 2;
        float l0a = 0.f, l1a = 0.f, l0b = 0.f, l1b = 0.f;
        #pragma unroll
        for (int nt = 0; nt < 8; nt++) {
            int c = nt*8 + q2;
            float b0 = sbc2[c], b1 = sbc2[c+1];
            float w00 = sWc3[2*c],     w01 = sWc3[2*c+1];
            float w10 = sWc3[2*c+2],   w11 = sWc3[2*c+3];
            float za = fmaxf(acc2[nt][0] + b0, 0.f);
            float zb = fmaxf(acc2[nt][1] + b1, 0.f);
            l0a += za*w00 + zb*w10;
            l1a += za*w01 + zb*w11;
            float zc = fmaxf(acc2[nt][2] + b0, 0.f);
            float zd = fmaxf(acc2[nt][3] + b1, 0.f);
            l0b += zc*w00 + zd*w10;
            l1b += zc*w01 + zd*w11;
        }
        #pragma unroll
        for (int off = 1; off <= 2; off <<= 1) {
            l0a += __shfl_xor_sync(0xFFFFFFFFu, l0a, off);
            l1a += __shfl_xor_sync(0xFFFFFFFFu, l1a, off);
            l0b += __shfl_xor_sync(0xFFFFFFFFu, l0b, off);
            l1b += __shfl_xor_sync(0xFFFFFFFFu, l1b, off);
        }
        if ((lane & 3) == 0) {
            float c3a = __ldg(bc3 + 0), c3b = __ldg(bc3 + 1);
            float L0 = l0a + c3a, L1 = l1a + c3b;
            float mx = fmaxf(L0, L1);
            float lse = mx + logf(expf(L0 - mx) + expf(L1 - mx));
            size_t o = (size_t)(e0 + r0) * 2;
            out[o + 0] = L0 - lse;
            out[o + 1] = L1 - lse;
            L0 = l0b + c3a; L1 = l1b + c3b;
            mx = fmaxf(L0, L1);
            lse = mx + logf(expf(L0 - mx) + expf(L1 - mx));
            o = (size_t)(e0 + r0 + 8) * 2;
            out[o + 0] = L0 - lse;
            out[o + 1] = L1 - lse;
        }
    }
}

// ---------------- launch ----------------
extern "C" void kernel_launch(void* const* d_in, const int* in_sizes, int n_in,
                              void* d_out, int out_size) {
    const float* x   = (const float*)d_in[0];
    const int*   ei  = (const int*)  d_in[1];
    const float* ea  = (const float*)d_in[2];
    const float* W1  = (const float*)d_in[3];
    const float* b1  = (const float*)d_in[4];
    const float* W2  = (const float*)d_in[5];
    const float* b2  = (const float*)d_in[6];
    const float* W3  = (const float*)d_in[7];
    const float* b3  = (const float*)d_in[8];
    const float* We1 = (const float*)d_in[9];
    const float* be1 = (const float*)d_in[10];
    const float* We2 = (const float*)d_in[11];
    const float* be2 = (const float*)d_in[12];
    const float* Wc1 = (const float*)d_in[13];
    const float* bc1 = (const float*)d_in[14];
    const float* Wc2 = (const float*)d_in[15];
    const float* bc2 = (const float*)d_in[16];
    const float* Wc3 = (const float*)d_in[17];
    const float* bc3 = (const float*)d_in[18];
    float* out = (float*)d_out;
    const int* row = ei;
    const int* col = ei + NE;

    float *h1, *h2, *t;
    __nv_bfloat16 *tb;
    cudaGetSymbolAddress((void**)&h1, g_h1);
    cudaGetSymbolAddress((void**)&h2, g_h2);
    cudaGetSymbolAddress((void**)&t,  g_t);
    cudaGetSymbolAddress((void**)&tb, g_tb);
    __nv_bfloat16 *wb2, *wb3, *wbu, *wbv;
    cudaGetSymbolAddress((void**)&wb2, g_Wb2);
    cudaGetSymbolAddress((void**)&wb3, g_Wb3);
    cudaGetSymbolAddress((void**)&wbu, g_WbU);
    cudaGetSymbolAddress((void**)&wbv, g_WbV);

    cudaFuncSetAttribute(k_node_mma, cudaFuncAttributeMaxDynamicSharedMemorySize, SMEM_NODE_BYTES);
    cudaFuncSetAttribute(k_edge_mlp, cudaFuncAttributeMaxDynamicSharedMemorySize, SMEM_EDGE_BYTES);

    // graph preprocessing
    k_deg_zero <<<(NN + 255)/256, 256>>>();
    k_deg_count<<<(NE + 255)/256, 256>>>(col);
    k_scanA    <<<NCHUNK, 1024>>>();
    k_scanB    <<<1, 64>>>();
    k_scanC    <<<(NN + 255)/256, 256>>>();
    k_fill     <<<(NE + 255)/256, 256>>>(row, col);
    k_prep     <<<352, 256>>>(We2, Wc1, be2, bc1, Wc2, W2, W3);

    const int NB = (NN + 127)/128;
    // layer 1
    k_transform1<<<(NN + 63)/64, 128>>>(x, W1, tb);
    k_aggregate <<<NN/8, 256>>>(tb, b1, h1);
    // layer 2
    k_node_mma  <<<NB, 256, SMEM_NODE_BYTES>>>(h1, wb2, tb, nullptr);
    k_aggregate <<<NN/8, 256>>>(tb, b2, h2);
    // layer 3
    k_node_mma  <<<NB, 256, SMEM_NODE_BYTES>>>(h2, wb3, tb, nullptr);
    k_aggregate <<<NN/8, 256>>>(tb, b3, h1);

    // U = h@Wc1[0:128] -> t,  V = h@Wc1[128:256] -> h2
    k_node_mma  <<<NB, 256, SMEM_NODE_BYTES>>>(h1, wbu, nullptr, t);
    k_node_mma  <<<NB, 256, SMEM_NODE_BYTES>>>(h1, wbv, nullptr, h2);

    k_edge_mlp<<<NE/EB, 256, SMEM_EDGE_BYTES>>>(row, col, ea, We1, be1,
                                                bc2, Wc3, bc3, t, h2, out);
}

// round 7
// speedup vs baseline: 4.6769x; 1.1530x over previous
#include <cuda_runtime.h>
#include <cuda_bf16.h>
#include <math.h>
#include <stdint.h>

#define NN 50000
#define NE 800000
#define HD 128
#define FNI 8
#define FEI 4
#define EB 128          // edges per tile in edge MLP
#define NTILES (NE/EB)  // 6250
#define EGRID 1184      // persistent-ish edge blocks
#define NCHUNK 49       // ceil(NN/1024)

// ---------------- device scratch (no allocations allowed) ----------------
__device__ int   g_deg[NN];
__device__ int   g_off[NN+1];
__device__ int   g_cur[NN];
__device__ int   g_src[NE];
__device__ int   g_bsum[NCHUNK];
__device__ float g_dinv[NN];
__device__ float g_h1[NN*HD];  // h accumulator A (fp32)
__device__ float g_h2[NN*HD];  // h accumulator B (fp32)
__device__ __nv_bfloat16 g_tb[NN*HD];   // bf16 message buffer
__device__ __nv_bfloat16 g_Ub[NN*HD];   // bf16 U = h@Wc1[0:128]
__device__ __nv_bfloat16 g_Vb[NN*HD];   // bf16 V = h@Wc1[128:256]
__device__ float g_c1p[HD];    // bc1 + be2 @ Wc1[256:384]
__device__ __nv_bfloat16 g_B1[HD*HD];   // M = We2@Wc1c, row-major [k][n], bf16
__device__ __nv_bfloat16 g_B2[HD*64];   // Wc2 row-major [k][n], bf16
__device__ __nv_bfloat16 g_Wb2[HD*HD];  // bf16 W2
__device__ __nv_bfloat16 g_Wb3[HD*HD];  // bf16 W3
__device__ __nv_bfloat16 g_WbU[HD*HD];  // bf16 Wc1[0:128]
__device__ __nv_bfloat16 g_WbV[HD*HD];  // bf16 Wc1[128:256]

// ---------------- PTX helpers ----------------
__device__ __forceinline__ uint32_t smem_u32(const void* p) {
    uint32_t a;
    asm("{ .reg .u64 t; cvta.to.shared.u64 t, %1; cvt.u32.u64 %0, t; }" : "=r"(a) : "l"(p));
    return a;
}
__device__ __forceinline__ void ldsm_x4(uint32_t* r, uint32_t addr) {
    asm volatile("ldmatrix.sync.aligned.m8n8.x4.shared.b16 {%0,%1,%2,%3}, [%4];"
        : "=r"(r[0]), "=r"(r[1]), "=r"(r[2]), "=r"(r[3]) : "r"(addr));
}
__device__ __forceinline__ void ldsm_x4_t(uint32_t* r, uint32_t addr) {
    asm volatile("ldmatrix.sync.aligned.m8n8.x4.trans.shared.b16 {%0,%1,%2,%3}, [%4];"
        : "=r"(r[0]), "=r"(r[1]), "=r"(r[2]), "=r"(r[3]) : "r"(addr));
}
__device__ __forceinline__ void mma_bf16(float* d, const uint32_t* a, uint32_t b0, uint32_t b1) {
    asm volatile("mma.sync.aligned.m16n8k16.row.col.f32.bf16.bf16.f32 "
        "{%0,%1,%2,%3}, {%4,%5,%6,%7}, {%8,%9}, {%0,%1,%2,%3};"
        : "+f"(d[0]), "+f"(d[1]), "+f"(d[2]), "+f"(d[3])
        : "r"(a[0]), "r"(a[1]), "r"(a[2]), "r"(a[3]), "r"(b0), "r"(b1));
}
__device__ __forceinline__ uint32_t pack_bf16x2(float lo, float hi) {
    uint32_t p;
    asm("cvt.rn.bf16x2.f32 %0, %1, %2;" : "=r"(p) : "f"(hi), "f"(lo));
    return p;
}
__device__ __forceinline__ void acc_bf16x2(uint32_t u, float& lo, float& hi) {
    lo += __uint_as_float(u << 16);
    hi += __uint_as_float(u & 0xFFFF0000u);
}
__device__ __forceinline__ float bf_lo(uint32_t u) { return __uint_as_float(u << 16); }
__device__ __forceinline__ float bf_hi(uint32_t u) { return __uint_as_float(u & 0xFFFF0000u); }

// ---------------- degree / norm / CSR ----------------
__global__ void k_deg_zero() {
    int i = blockIdx.x*blockDim.x + threadIdx.x;
    if (i < NN) g_deg[i] = 0;
}
__global__ void k_deg_count(const int* __restrict__ col) {
    int i = blockIdx.x*blockDim.x + threadIdx.x;
    if (i < NE) atomicAdd(&g_deg[col[i]], 1);
}
// phase A: per-chunk exclusive scan (+dinv)
__global__ __launch_bounds__(1024) void k_scanA() {
    __shared__ int ws[32];
    int tid = threadIdx.x, lane = tid & 31, w = tid >> 5;
    int i = blockIdx.x*1024 + tid;
    int v = (i < NN) ? g_deg[i] : 0;
    if (i < NN) g_dinv[i] = rsqrtf((float)(v + 1));  // +1 self loop
    int x = v;
    #pragma unroll
    for (int d = 1; d < 32; d <<= 1) {
        int y = __shfl_up_sync(0xFFFFFFFFu, x, d);
        if (lane >= d) x += y;
    }
    if (lane == 31) ws[w] = x;
    __syncthreads();
    if (w == 0) {
        int y = ws[lane];
        #pragma unroll
        for (int d = 1; d < 32; d <<= 1) {
            int z = __shfl_up_sync(0xFFFFFFFFu, y, d);
            if (lane >= d) y += z;
        }
        ws[lane] = y;
    }
    __syncthreads();
    int excl = x - v + (w > 0 ? ws[w-1] : 0);
    if (i < NN) g_off[i] = excl;
    if (tid == 1023) g_bsum[blockIdx.x] = ws[31];
}
__global__ void k_scanB() {
    __shared__ int wtot[2];
    int tid = threadIdx.x, lane = tid & 31, w = tid >> 5;
    int v = (tid < NCHUNK) ? g_bsum[tid] : 0;
    int x = v;
    #pragma unroll
    for (int d = 1; d < 32; d <<= 1) {
        int y = __shfl_up_sync(0xFFFFFFFFu, x, d);
        if (lane >= d) x += y;
    }
    if (lane == 31) wtot[w] = x;
    __syncthreads();
    if (w == 1) x += wtot[0];
    if (tid < NCHUNK) g_bsum[tid] = x - v;
    if (tid == 0) g_off[NN] = wtot[0] + wtot[1];
}
__global__ void k_scanC() {
    int i = blockIdx.x*blockDim.x + threadIdx.x;
    if (i < NN) {
        int o = g_off[i] + g_bsum[i >> 10];
        g_off[i] = o;
        g_cur[i] = o;
    }
}
__global__ void k_fill(const int* __restrict__ row, const int* __restrict__ col) {
    int i = blockIdx.x*blockDim.x + threadIdx.x;
    if (i < NE) {
        int pos = atomicAdd(&g_cur[col[i]], 1);
        g_src[pos] = row[i];
    }
}

// ---------------- precompute: folded weights + bf16 weights ----------------
__global__ void k_prep(const float* __restrict__ We2, const float* __restrict__ Wc1,
                       const float* __restrict__ be2, const float* __restrict__ bc1,
                       const float* __restrict__ Wc2, const float* __restrict__ W2,
                       const float* __restrict__ W3) {
    int idx = blockIdx.x*256 + threadIdx.x;   // 0..90111
    const float* Wc1c = Wc1 + 256*HD;
    if (idx < 16384) {
        int k = idx >> 7, n = idx & 127;
        float s = 0.f;
        for (int j = 0; j < HD; j++) s += __ldg(We2 + k*HD + j) * __ldg(Wc1c + j*HD + n);
        g_B1[idx] = __float2bfloat16(s);
        if (idx < 128) {
            float c = __ldg(bc1 + idx);
            for (int j = 0; j < HD; j++) c += __ldg(be2 + j) * __ldg(Wc1c + j*HD + idx);
            g_c1p[idx] = c;
        }
    } else if (idx < 24576) {
        int t = idx - 16384;
        g_B2[t] = __float2bfloat16(__ldg(Wc2 + t));
    } else if (idx < 40960) {
        int t = idx - 24576;
        g_Wb2[t] = __float2bfloat16(__ldg(W2 + t));
    } else if (idx < 57344) {
        int t = idx - 40960;
        g_Wb3[t] = __float2bfloat16(__ldg(W3 + t));
    } else if (idx < 73728) {
        int t = idx - 57344;
        g_WbU[t] = __float2bfloat16(__ldg(Wc1 + t));
    } else if (idx < 90112) {
        int t = idx - 73728;
        g_WbV[t] = __float2bfloat16(__ldg(Wc1 + HD*HD + t));
    }
}

// ---------------- layer-1 transform (K=8): tb = bf16(dinv * (x@W1)) ----------------
__global__ void k_transform1(const float* __restrict__ x, const float* __restrict__ W1,
                             __nv_bfloat16* __restrict__ tout) {
    __shared__ float sx[64*FNI];
    __shared__ float sw[FNI*HD];
    int tid = threadIdx.x;  // 0..127
    for (int i = tid; i < FNI*HD; i += 128) sw[i] = W1[i];
    int r0 = blockIdx.x * 64;
    for (int i = tid; i < 64*FNI; i += 128) {
        int r = r0 + (i >> 3);
        sx[i] = (r < NN) ? x[r*FNI + (i & 7)] : 0.f;
    }
    __syncthreads();
    int c = (tid & 63) * 2;
    int half = tid >> 6;
    for (int m = half*32; m < half*32 + 32; m++) {
        int r = r0 + m;
        if (r >= NN) break;
        float a0 = 0.f, a1 = 0.f;
        #pragma unroll
        for (int k = 0; k < FNI; k++) {
            float xv = sx[m*FNI + k];
            a0 += xv * sw[k*HD + c];
            a1 += xv * sw[k*HD + c + 1];
        }
        float d = g_dinv[r];
        ((uint32_t*)tout)[(size_t)r*64 + (c >> 1)] = pack_bf16x2(d*a0, d*a1);
    }
}

// ---------------- node GEMM via mma.sync bf16: outb = bf16((A@Wb) [*dinv]) ----------------
#define NSTR 136
#define O_NW 34816
#define SMEM_NODE_BYTES 69632

__global__ __launch_bounds__(256, 2) void k_node_mma(const float* __restrict__ A,
        const __nv_bfloat16* __restrict__ Wb,
        __nv_bfloat16* __restrict__ outb, int scaled) {
    extern __shared__ char smem[];
    uint32_t sbase = smem_u32(smem);
    uint32_t* sAu = (uint32_t*)smem;
    uint32_t* sWu = (uint32_t*)(smem + O_NW);
    int tid = threadIdx.x, wid = tid >> 5, lane = tid & 31;
    int r0 = blockIdx.x * 128;

    const uint32_t* wsrc = (const uint32_t*)Wb;
    for (int i = tid; i < 8192; i += 256) {
        int r = i >> 6, cp = i & 63;
        sWu[r*(NSTR/2) + cp] = __ldg(wsrc + i);
    }
    for (int i = tid; i < 8192; i += 256) {
        int m = i >> 6, kp = i & 63;
        int r = r0 + m; if (r >= NN) r = NN - 1;
        float2 v = __ldg((const float2*)(A + (size_t)r*HD) + kp);
        sAu[m*(NSTR/2) + kp] = pack_bf16x2(v.x, v.y);
    }
    __syncthreads();

    int lr = lane & 15, lc = (lane >> 4) << 3;
    float acc[16][4];
    #pragma unroll
    for (int i = 0; i < 16; i++)
        #pragma unroll
        for (int j = 0; j < 4; j++) acc[i][j] = 0.f;
    #pragma unroll
    for (int k0 = 0; k0 < 8; k0++) {
        uint32_t a[4];
        ldsm_x4(a, sbase + ((16*wid + lr)*NSTR + k0*16 + lc)*2);
        #pragma unroll
        for (int nt2 = 0; nt2 < 8; nt2++) {
            uint32_t b[4];
            ldsm_x4_t(b, sbase + O_NW + ((k0*16 + lr)*NSTR + nt2*16 + lc)*2);
            mma_bf16(acc[2*nt2],     a, b[0], b[1]);
            mma_bf16(acc[2*nt2 + 1], a, b[2], b[3]);
        }
    }

    int rA = r0 + 16*wid + (lane >> 2);
    int rB = rA + 8;
    int q = lane & 3;
    if (rA < NN) {
        float s = scaled ? g_dinv[rA] : 1.f;
        uint32_t* ob = (uint32_t*)outb + (size_t)rA*64;
        #pragma unroll
        for (int nt = 0; nt < 16; nt++)
            ob[nt*4 + q] = pack_bf16x2(acc[nt][0]*s, acc[nt][1]*s);
    }
    if (rB < NN) {
        float s = scaled ? g_dinv[rB] : 1.f;
        uint32_t* ob = (uint32_t*)outb + (size_t)rB*64;
        #pragma unroll
        for (int nt = 0; nt < 16; nt++)
            ob[nt*4 + q] = pack_bf16x2(acc[nt][2]*s, acc[nt][3]*s);
    }
}

// ---------------- CSR gather-aggregate (bf16 messages, unroll-4 MLP) ----------------
__global__ __launch_bounds__(256) void k_aggregate(const __nv_bfloat16* __restrict__ t,
        const float* __restrict__ b, float* __restrict__ outp) {
    int wid = threadIdx.x >> 5, lane = threadIdx.x & 31;
    int c = blockIdx.x * 8 + wid;
    int start = __ldg(&g_off[c]), end = __ldg(&g_off[c+1]);
    const uint2* T = (const uint2*)t;   // 32 uint2 per row (128 bf16)
    float ax = 0.f, ay = 0.f, az = 0.f, aw = 0.f;
    {   // self term
        uint2 sv = __ldg(T + (size_t)c*32 + lane);
        acc_bf16x2(sv.x, ax, ay);
        acc_bf16x2(sv.y, az, aw);
    }
    for (int base = start; base < end; base += 32) {
        int n = end - base;
        int myIdx = (lane < n) ? __ldg(&g_src[base + lane]) : 0;
        int cnt = min(32, n);
        int j = 0;
        for (; j + 4 <= cnt; j += 4) {
            int r0 = __shfl_sync(0xFFFFFFFFu, myIdx, j);
            int r1 = __shfl_sync(0xFFFFFFFFu, myIdx, j+1);
            int r2 = __shfl_sync(0xFFFFFFFFu, myIdx, j+2);
            int r3 = __shfl_sync(0xFFFFFFFFu, myIdx, j+3);
            uint2 v0 = __ldg(T + (size_t)r0*32 + lane);
            uint2 v1 = __ldg(T + (size_t)r1*32 + lane);
            uint2 v2 = __ldg(T + (size_t)r2*32 + lane);
            uint2 v3 = __ldg(T + (size_t)r3*32 + lane);
            acc_bf16x2(v0.x, ax, ay); acc_bf16x2(v0.y, az, aw);
            acc_bf16x2(v1.x, ax, ay); acc_bf16x2(v1.y, az, aw);
            acc_bf16x2(v2.x, ax, ay); acc_bf16x2(v2.y, az, aw);
            acc_bf16x2(v3.x, ax, ay); acc_bf16x2(v3.y, az, aw);
        }
        for (; j < cnt; j++) {
            int r = __shfl_sync(0xFFFFFFFFu, myIdx, j);
            uint2 v = __ldg(T + (size_t)r*32 + lane);
            acc_bf16x2(v.x, ax, ay);
            acc_bf16x2(v.y, az, aw);
        }
    }
    float d = g_dinv[c];
    float4 bb = __ldg((const float4*)b + lane);
    float4 o;
    o.x = fmaxf(d*ax + bb.x, 0.f);
    o.y = fmaxf(d*ay + bb.y, 0.f);
    o.z = fmaxf(d*az + bb.z, 0.f);
    o.w = fmaxf(d*aw + bb.w, 0.f);
    *((float4*)(outp + (size_t)c*HD) + lane) = o;
}

// ---------------- fused edge MLP, mma.sync bf16, multi-tile ----------------
#define SAS 136
#define SBS 72
#define O_SA    0
#define O_SB1   34816
#define O_SB2   69632
#define O_SEA   88064
#define O_SWE1  90112
#define O_SBE1  92160
#define O_SC1P  92672
#define O_SWC3  93184
#define O_SBC2  93696
#define O_SIDX  93952
#define SMEM_EDGE_BYTES 94976

__global__ __launch_bounds__(256, 2) void k_edge_mlp(
        const int* __restrict__ row, const int* __restrict__ col,
        const float* __restrict__ ea,
        const float* __restrict__ We1, const float* __restrict__ be1,
        const float* __restrict__ bc2, const float* __restrict__ Wc3,
        const float* __restrict__ bc3,
        const uint32_t* __restrict__ U, const uint32_t* __restrict__ V,
        float* __restrict__ out) {
    extern __shared__ char smem[];
    uint32_t sbase = smem_u32(smem);
    int tid = threadIdx.x;
    int wid = tid >> 5, lane = tid & 31;

    float* sEA  = (float*)(smem + O_SEA);
    float* sWe1 = (float*)(smem + O_SWE1);
    float* sbe1 = (float*)(smem + O_SBE1);
    float* sC1p = (float*)(smem + O_SC1P);
    float* sWc3 = (float*)(smem + O_SWC3);
    float* sbc2 = (float*)(smem + O_SBC2);
    int*   sIdx = (int*)(smem + O_SIDX);
    uint32_t* sA1u = (uint32_t*)(smem + O_SA);
    uint32_t* sB1u = (uint32_t*)(smem + O_SB1);
    uint32_t* sB2u = (uint32_t*)(smem + O_SB2);

    // ---- persistent loads (once per block) ----
    if (tid < 128) {
        sbe1[tid] = __ldg(be1 + tid);
        sC1p[tid] = g_c1p[tid];
        sWc3[tid] = __ldg(Wc3 + tid);
        if (tid < 64) sbc2[tid] = __ldg(bc2 + tid);
    }
    for (int i = tid; i < 512; i += 256) sWe1[i] = __ldg(We1 + i);
    {
        const uint32_t* src = (const uint32_t*)g_B1;
        for (int i = tid; i < 8192; i += 256) {
            int r = i >> 6, cp = i & 63;
            sB1u[r*(SAS/2) + cp] = __ldg(src + i);
        }
    }
    {
        const uint32_t* src = (const uint32_t*)g_B2;
        for (int i = tid; i < 4096; i += 256) {
            int r = i >> 5, cp = i & 31;
            sB2u[r*(SBS/2) + cp] = __ldg(src + i);
        }
    }

    int lr = lane & 15, lc = (lane >> 4) << 3;
    float c3a = __ldg(bc3 + 0), c3b = __ldg(bc3 + 1);

    for (int tile = blockIdx.x; tile < NTILES; tile += EGRID) {
        int e0 = tile * EB;
        __syncthreads();   // protect sIdx/sEA/sA from previous tile's readers
        if (tid < 128) {
            sIdx[tid]       = __ldg(row + e0 + tid);
            sIdx[128 + tid] = __ldg(col + e0 + tid);
        }
        for (int i = tid; i < 512; i += 256)
            sEA[i] = __ldg(ea + (size_t)e0*4 + i);
        __syncthreads();

        // a = relu(ea@We1 + be1) -> bf16 sA
        for (int i = tid; i < 128*64; i += 256) {
            int m = i >> 6, kp = i & 63; int k = kp << 1;
            float ev0 = sEA[m*4+0], ev1 = sEA[m*4+1], ev2 = sEA[m*4+2], ev3 = sEA[m*4+3];
            float a0 = sbe1[k]   + ev0*sWe1[k]     + ev1*sWe1[128+k]   + ev2*sWe1[256+k]   + ev3*sWe1[384+k];
            float a1 = sbe1[k+1] + ev0*sWe1[k+1]   + ev1*sWe1[128+k+1] + ev2*sWe1[256+k+1] + ev3*sWe1[384+k+1];
            sA1u[m*(SAS/2) + kp] = pack_bf16x2(fmaxf(a0, 0.f), fmaxf(a1, 0.f));
        }
        __syncthreads();

        // GEMM1: D[128,128] = a @ M
        float acc[16][4];
        #pragma unroll
        for (int i = 0; i < 16; i++)
            #pragma unroll
            for (int j = 0; j < 4; j++) acc[i][j] = 0.f;
        #pragma unroll
        for (int k0 = 0; k0 < 8; k0++) {
            uint32_t a[4];
            ldsm_x4(a, sbase + O_SA + ((16*wid + lr)*SAS + k0*16 + lc)*2);
            #pragma unroll
            for (int nt2 = 0; nt2 < 8; nt2++) {
                uint32_t b[4];
                ldsm_x4_t(b, sbase + O_SB1 + ((k0*16 + lr)*SAS + nt2*16 + lc)*2);
                mma_bf16(acc[2*nt2],     a, b[0], b[1]);
                mma_bf16(acc[2*nt2 + 1], a, b[2], b[3]);
            }
        }
        __syncthreads();

        // epilogue1: z1 = relu(D + U[row] + V[col] + c1p) -> bf16 sA
        {
            int r0 = 16*wid + (lane >> 2);
            int q = lane & 3;
            int rI0 = sIdx[r0],     cI0 = sIdx[128 + r0];
            int rI1 = sIdx[r0 + 8], cI1 = sIdx[128 + r0 + 8];
            const uint32_t* U0 = U + (size_t)rI0*64;
            const uint32_t* V0 = V + (size_t)cI0*64;
            const uint32_t* U1 = U + (size_t)rI1*64;
            const uint32_t* V1 = V + (size_t)cI1*64;
            #pragma unroll
            for (int nt = 0; nt < 16; nt++) {
                int cw = nt*4 + q;          // uint32 index; cols 2cw, 2cw+1
                uint32_t uw0 = __ldg(U0 + cw), vw0 = __ldg(V0 + cw);
                uint32_t uw1 = __ldg(U1 + cw), vw1 = __ldg(V1 + cw);
                int c = cw*2;
                float p0 = sC1p[c], p1 = sC1p[c+1];
                float z0 = fmaxf(acc[nt][0] + bf_lo(uw0) + bf_lo(vw0) + p0, 0.f);
                float z1 = fmaxf(acc[nt][1] + bf_hi(uw0) + bf_hi(vw0) + p1, 0.f);
                float z2 = fmaxf(acc[nt][2] + bf_lo(uw1) + bf_lo(vw1) + p0, 0.f);
                float z3 = fmaxf(acc[nt][3] + bf_hi(uw1) + bf_hi(vw1) + p1, 0.f);
                sA1u[r0*(SAS/2) + cw]     = pack_bf16x2(z0, z1);
                sA1u[(r0+8)*(SAS/2) + cw] = pack_bf16x2(z2, z3);
            }
        }
        __syncthreads();

        // GEMM2: D2[128,64] = z1 @ Wc2
        float acc2[8][4];
        #pragma unroll
        for (int i = 0; i < 8; i++)
            #pragma unroll
            for (int j = 0; j < 4; j++) acc2[i][j] = 0.f;
        #pragma unroll
        for (int k0 = 0; k0 < 8; k0++) {
            uint32_t a[4];
            ldsm_x4(a, sbase + O_SA + ((16*wid + lr)*SAS + k0*16 + lc)*2);
            #pragma unroll
            for (int nt2 = 0; nt2 < 4; nt2++) {
                uint32_t b[4];
                ldsm_x4_t(b, sbase + O_SB2 + ((k0*16 + lr)*SBS + nt2*16 + lc)*2);
                mma_bf16(acc2[2*nt2],     a, b[0], b[1]);
                mma_bf16(acc2[2*nt2 + 1], a, b[2], b[3]);
            }
        }

        // epilogue2: z2 = relu(D2 + bc2); logits; log_softmax
        {
            int r0 = 16*wid + (lane >> 2);
            int q2 = (lane & 3) * 2;
            float l0a = 0.f, l1a = 0.f, l0b = 0.f, l1b = 0.f;
            #pragma unroll
            for (int nt = 0; nt < 8; nt++) {
                int c = nt*8 + q2;
                float b0 = sbc2[c], b1 = sbc2[c+1];
                float w00 = sWc3[2*c],     w01 = sWc3[2*c+1];
                float w10 = sWc3[2*c+2],   w11 = sWc3[2*c+3];
                float za = fmaxf(acc2[nt][0] + b0, 0.f);
                float zb = fmaxf(acc2[nt][1] + b1, 0.f);
                l0a += za*w00 + zb*w10;
                l1a += za*w01 + zb*w11;
                float zc = fmaxf(acc2[nt][2] + b0, 0.f);
                float zd = fmaxf(acc2[nt][3] + b1, 0.f);
                l0b += zc*w00 + zd*w10;
                l1b += zc*w01 + zd*w11;
            }
            #pragma unroll
            for (int off = 1; off <= 2; off <<= 1) {
                l0a += __shfl_xor_sync(0xFFFFFFFFu, l0a, off);
                l1a += __shfl_xor_sync(0xFFFFFFFFu, l1a, off);
                l0b += __shfl_xor_sync(0xFFFFFFFFu, l0b, off);
                l1b += __shfl_xor_sync(0xFFFFFFFFu, l1b, off);
            }
            if ((lane & 3) == 0) {
                float L0 = l0a + c3a, L1 = l1a + c3b;
                float mx = fmaxf(L0, L1);
                float lse = mx + logf(expf(L0 - mx) + expf(L1 - mx));
                size_t o = (size_t)(e0 + r0) * 2;
                out[o + 0] = L0 - lse;
                out[o + 1] = L1 - lse;
                L0 = l0b + c3a; L1 = l1b + c3b;
                mx = fmaxf(L0, L1);
                lse = mx + logf(expf(L0 - mx) + expf(L1 - mx));
                o = (size_t)(e0 + r0 + 8) * 2;
                out[o + 0] = L0 - lse;
                out[o + 1] = L1 - lse;
            }
        }
    }
}

// ---------------- launch ----------------
extern "C" void kernel_launch(void* const* d_in, const int* in_sizes, int n_in,
                              void* d_out, int out_size) {
    const float* x   = (const float*)d_in[0];
    const int*   ei  = (const int*)  d_in[1];
    const float* ea  = (const float*)d_in[2];
    const float* W1  = (const float*)d_in[3];
    const float* b1  = (const float*)d_in[4];
    const float* W2  = (const float*)d_in[5];
    const float* b2  = (const float*)d_in[6];
    const float* W3  = (const float*)d_in[7];
    const float* b3  = (const float*)d_in[8];
    const float* We1 = (const float*)d_in[9];
    const float* be1 = (const float*)d_in[10];
    const float* We2 = (const float*)d_in[11];
    const float* be2 = (const float*)d_in[12];
    const float* Wc1 = (const float*)d_in[13];
    const float* bc1 = (const float*)d_in[14];
    const float* Wc2 = (const float*)d_in[15];
    const float* bc2 = (const float*)d_in[16];
    const float* Wc3 = (const float*)d_in[17];
    const float* bc3 = (const float*)d_in[18];
    float* out = (float*)d_out;
    const int* row = ei;
    const int* col = ei + NE;

    float *h1, *h2;
    __nv_bfloat16 *tb, *ub, *vb;
    cudaGetSymbolAddress((void**)&h1, g_h1);
    cudaGetSymbolAddress((void**)&h2, g_h2);
    cudaGetSymbolAddress((void**)&tb, g_tb);
    cudaGetSymbolAddress((void**)&ub, g_Ub);
    cudaGetSymbolAddress((void**)&vb, g_Vb);
    __nv_bfloat16 *wb2, *wb3, *wbu, *wbv;
    cudaGetSymbolAddress((void**)&wb2, g_Wb2);
    cudaGetSymbolAddress((void**)&wb3, g_Wb3);
    cudaGetSymbolAddress((void**)&wbu, g_WbU);
    cudaGetSymbolAddress((void**)&wbv, g_WbV);

    cudaFuncSetAttribute(k_node_mma, cudaFuncAttributeMaxDynamicSharedMemorySize, SMEM_NODE_BYTES);
    cudaFuncSetAttribute(k_edge_mlp, cudaFuncAttributeMaxDynamicSharedMemorySize, SMEM_EDGE_BYTES);

    // graph preprocessing
    k_deg_zero <<<(NN + 255)/256, 256>>>();
    k_deg_count<<<(NE + 255)/256, 256>>>(col);
    k_scanA    <<<NCHUNK, 1024>>>();
    k_scanB    <<<1, 64>>>();
    k_scanC    <<<(NN + 255)/256, 256>>>();
    k_fill     <<<(NE + 255)/256, 256>>>(row, col);
    k_prep     <<<352, 256>>>(We2, Wc1, be2, bc1, Wc2, W2, W3);

    const int NB = (NN + 127)/128;
    // layer 1
    k_transform1<<<(NN + 63)/64, 128>>>(x, W1, tb);
    k_aggregate <<<NN/8, 256>>>(tb, b1, h1);
    // layer 2
    k_node_mma  <<<NB, 256, SMEM_NODE_BYTES>>>(h1, wb2, tb, 1);
    k_aggregate <<<NN/8, 256>>>(tb, b2, h2);
    // layer 3
    k_node_mma  <<<NB, 256, SMEM_NODE_BYTES>>>(h2, wb3, tb, 1);
    k_aggregate <<<NN/8, 256>>>(tb, b3, h1);

    // U = h@Wc1[0:128], V = h@Wc1[128:256]  (bf16)
    k_node_mma  <<<NB, 256, SMEM_NODE_BYTES>>>(h1, wbu, ub, 0);
    k_node_mma  <<<NB, 256, SMEM_NODE_BYTES>>>(h1, wbv, vb, 0);

    k_edge_mlp<<<EGRID, 256, SMEM_EDGE_BYTES>>>(row, col, ea, We1, be1,
                                                bc2, Wc3, bc3,
                                                (const uint32_t*)ub, (const uint32_t*)vb, out);
}

// round 9
// speedup vs baseline: 5.8415x; 1.2490x over previous
#include <cuda_runtime.h>
#include <cuda_bf16.h>
#include <math.h>
#include <stdint.h>

#define NN 50000
#define NE 800000
#define HD 128
#define FNI 8
#define FEI 4
#define EGRID 1184      // edge blocks (8 warps each, 16 edges per warp-tile)
#define NWT (NE/16)     // 50000 warp-tiles
#define NCHUNK 49       // ceil(NN/1024)

// ---------------- device scratch (no allocations allowed) ----------------
__device__ int   g_deg[NN];
__device__ int   g_off[NN+1];
__device__ int   g_cur[NN];
__device__ int   g_src[NE];
__device__ int   g_bsum[NCHUNK];
__device__ float g_dinv[NN];
__device__ float g_h1[NN*HD];  // h accumulator A (fp32)
__device__ float g_h2[NN*HD];  // h accumulator B (fp32)
__device__ __nv_bfloat16 g_tb[NN*HD];   // bf16 message buffer
__device__ __nv_bfloat16 g_Ub[NN*HD];   // bf16 U = h@Wc1[0:128]
__device__ __nv_bfloat16 g_Vb[NN*HD];   // bf16 V = h@Wc1[128:256]
__device__ float g_c1p[HD];    // bc1 + be2 @ Wc1[256:384]
__device__ __nv_bfloat16 g_B1[HD*HD];   // M = We2@Wc1c, row-major [k][n], bf16
__device__ __nv_bfloat16 g_B2[HD*64];   // Wc2 row-major [k][n], bf16
__device__ __nv_bfloat16 g_B0[16*HD];   // [We1; be1; 0] augmented-K, [k][n], bf16
__device__ __nv_bfloat16 g_Wb2[HD*HD];  // bf16 W2
__device__ __nv_bfloat16 g_Wb3[HD*HD];  // bf16 W3
__device__ __nv_bfloat16 g_WbU[HD*HD];  // bf16 Wc1[0:128]
__device__ __nv_bfloat16 g_WbV[HD*HD];  // bf16 Wc1[128:256]

// ---------------- PTX helpers ----------------
__device__ __forceinline__ uint32_t smem_u32(const void* p) {
    uint32_t a;
    asm("{ .reg .u64 t; cvta.to.shared.u64 t, %1; cvt.u32.u64 %0, t; }" : "=r"(a) : "l"(p));
    return a;
}
__device__ __forceinline__ void ldsm_x4(uint32_t* r, uint32_t addr) {
    asm volatile("ldmatrix.sync.aligned.m8n8.x4.shared.b16 {%0,%1,%2,%3}, [%4];"
        : "=r"(r[0]), "=r"(r[1]), "=r"(r[2]), "=r"(r[3]) : "r"(addr));
}
__device__ __forceinline__ void ldsm_x4_t(uint32_t* r, uint32_t addr) {
    asm volatile("ldmatrix.sync.aligned.m8n8.x4.trans.shared.b16 {%0,%1,%2,%3}, [%4];"
        : "=r"(r[0]), "=r"(r[1]), "=r"(r[2]), "=r"(r[3]) : "r"(addr));
}
__device__ __forceinline__ void mma_bf16(float* d, const uint32_t* a, uint32_t b0, uint32_t b1) {
    asm volatile("mma.sync.aligned.m16n8k16.row.col.f32.bf16.bf16.f32 "
        "{%0,%1,%2,%3}, {%4,%5,%6,%7}, {%8,%9}, {%0,%1,%2,%3};"
        : "+f"(d[0]), "+f"(d[1]), "+f"(d[2]), "+f"(d[3])
        : "r"(a[0]), "r"(a[1]), "r"(a[2]), "r"(a[3]), "r"(b0), "r"(b1));
}
__device__ __forceinline__ uint32_t pack_bf16x2(float lo, float hi) {
    uint32_t p;
    asm("cvt.rn.bf16x2.f32 %0, %1, %2;" : "=r"(p) : "f"(hi), "f"(lo));
    return p;
}
__device__ __forceinline__ void acc_bf16x2(uint32_t u, float& lo, float& hi) {
    lo += __uint_as_float(u << 16);
    hi += __uint_as_float(u & 0xFFFF0000u);
}
__device__ __forceinline__ float bf_lo(uint32_t u) { return __uint_as_float(u << 16); }
__device__ __forceinline__ float bf_hi(uint32_t u) { return __uint_as_float(u & 0xFFFF0000u); }

// ---------------- degree / norm / CSR ----------------
__global__ void k_deg_zero() {
    int i = blockIdx.x*blockDim.x + threadIdx.x;
    if (i < NN) g_deg[i] = 0;
}
__global__ void k_deg_count(const int* __restrict__ col) {
    int i = blockIdx.x*blockDim.x + threadIdx.x;
    if (i < NE) atomicAdd(&g_deg[col[i]], 1);
}
__global__ __launch_bounds__(1024) void k_scanA() {
    __shared__ int ws[32];
    int tid = threadIdx.x, lane = tid & 31, w = tid >> 5;
    int i = blockIdx.x*1024 + tid;
    int v = (i < NN) ? g_deg[i] : 0;
    if (i < NN) g_dinv[i] = rsqrtf((float)(v + 1));  // +1 self loop
    int x = v;
    #pragma unroll
    for (int d = 1; d < 32; d <<= 1) {
        int y = __shfl_up_sync(0xFFFFFFFFu, x, d);
        if (lane >= d) x += y;
    }
    if (lane == 31) ws[w] = x;
    __syncthreads();
    if (w == 0) {
        int y = ws[lane];
        #pragma unroll
        for (int d = 1; d < 32; d <<= 1) {
            int z = __shfl_up_sync(0xFFFFFFFFu, y, d);
            if (lane >= d) y += z;
        }
        ws[lane] = y;
    }
    __syncthreads();
    int excl = x - v + (w > 0 ? ws[w-1] : 0);
    if (i < NN) g_off[i] = excl;
    if (tid == 1023) g_bsum[blockIdx.x] = ws[31];
}
__global__ void k_scanB() {
    __shared__ int wtot[2];
    int tid = threadIdx.x, lane = tid & 31, w = tid >> 5;
    int v = (tid < NCHUNK) ? g_bsum[tid] : 0;
    int x = v;
    #pragma unroll
    for (int d = 1; d < 32; d <<= 1) {
        int y = __shfl_up_sync(0xFFFFFFFFu, x, d);
        if (lane >= d) x += y;
    }
    if (lane == 31) wtot[w] = x;
    __syncthreads();
    if (w == 1) x += wtot[0];
    if (tid < NCHUNK) g_bsum[tid] = x - v;
    if (tid == 0) g_off[NN] = wtot[0] + wtot[1];
}
__global__ void k_scanC() {
    int i = blockIdx.x*blockDim.x + threadIdx.x;
    if (i < NN) {
        int o = g_off[i] + g_bsum[i >> 10];
        g_off[i] = o;
        g_cur[i] = o;
    }
}
__global__ void k_fill(const int* __restrict__ row, const int* __restrict__ col) {
    int i = blockIdx.x*blockDim.x + threadIdx.x;
    if (i < NE) {
        int pos = atomicAdd(&g_cur[col[i]], 1);
        g_src[pos] = row[i];
    }
}

// ---------------- precompute: folded weights + bf16 weights ----------------
__global__ void k_prep(const float* __restrict__ We2, const float* __restrict__ Wc1,
                       const float* __restrict__ be2, const float* __restrict__ bc1,
                       const float* __restrict__ Wc2, const float* __restrict__ W2,
                       const float* __restrict__ W3, const float* __restrict__ We1,
                       const float* __restrict__ be1) {
    int idx = blockIdx.x*256 + threadIdx.x;   // 0..92159
    const float* Wc1c = Wc1 + 256*HD;
    if (idx < 16384) {
        int k = idx >> 7, n = idx & 127;
        float s = 0.f;
        for (int j = 0; j < HD; j++) s += __ldg(We2 + k*HD + j) * __ldg(Wc1c + j*HD + n);
        g_B1[idx] = __float2bfloat16(s);
        if (idx < 128) {
            float c = __ldg(bc1 + idx);
            for (int j = 0; j < HD; j++) c += __ldg(be2 + j) * __ldg(Wc1c + j*HD + idx);
            g_c1p[idx] = c;
        }
    } else if (idx < 24576) {
        int t = idx - 16384;
        g_B2[t] = __float2bfloat16(__ldg(Wc2 + t));
    } else if (idx < 40960) {
        int t = idx - 24576;
        g_Wb2[t] = __float2bfloat16(__ldg(W2 + t));
    } else if (idx < 57344) {
        int t = idx - 40960;
        g_Wb3[t] = __float2bfloat16(__ldg(W3 + t));
    } else if (idx < 73728) {
        int t = idx - 57344;
        g_WbU[t] = __float2bfloat16(__ldg(Wc1 + t));
    } else if (idx < 90112) {
        int t = idx - 73728;
        g_WbV[t] = __float2bfloat16(__ldg(Wc1 + HD*HD + t));
    } else if (idx < 92160) {
        int e = idx - 90112;      // 16x128 augmented [We1; be1; 0]
        int k = e >> 7, n = e & 127;
        float v = (k < 4) ? __ldg(We1 + k*HD + n) : (k == 4 ? __ldg(be1 + n) : 0.f);
        g_B0[e] = __float2bfloat16(v);
    }
}

// ---------------- layer-1 transform (K=8): tb = bf16(dinv * (x@W1)) ----------------
__global__ void k_transform1(const float* __restrict__ x, const float* __restrict__ W1,
                             __nv_bfloat16* __restrict__ tout) {
    __shared__ float sx[64*FNI];
    __shared__ float sw[FNI*HD];
    int tid = threadIdx.x;  // 0..127
    for (int i = tid; i < FNI*HD; i += 128) sw[i] = W1[i];
    int r0 = blockIdx.x * 64;
    for (int i = tid; i < 64*FNI; i += 128) {
        int r = r0 + (i >> 3);
        sx[i] = (r < NN) ? x[r*FNI + (i & 7)] : 0.f;
    }
    __syncthreads();
    int c = (tid & 63) * 2;
    int half = tid >> 6;
    for (int m = half*32; m < half*32 + 32; m++) {
        int r = r0 + m;
        if (r >= NN) break;
        float a0 = 0.f, a1 = 0.f;
        #pragma unroll
        for (int k = 0; k < FNI; k++) {
            float xv = sx[m*FNI + k];
            a0 += xv * sw[k*HD + c];
            a1 += xv * sw[k*HD + c + 1];
        }
        float d = g_dinv[r];
        ((uint32_t*)tout)[(size_t)r*64 + (c >> 1)] = pack_bf16x2(d*a0, d*a1);
    }
}

// ---------------- node GEMM via mma.sync bf16: outb = bf16((A@Wb) [*dinv]) ----------------
#define NSTR 136
#define O_NW 34816
#define SMEM_NODE_BYTES 69632

__global__ __launch_bounds__(256, 2) void k_node_mma(const float* __restrict__ A,
        const __nv_bfloat16* __restrict__ Wb,
        __nv_bfloat16* __restrict__ outb, int scaled) {
    extern __shared__ char smem[];
    uint32_t sbase = smem_u32(smem);
    uint32_t* sAu = (uint32_t*)smem;
    uint32_t* sWu = (uint32_t*)(smem + O_NW);
    int tid = threadIdx.x, wid = tid >> 5, lane = tid & 31;
    int r0 = blockIdx.x * 128;

    const uint32_t* wsrc = (const uint32_t*)Wb;
    for (int i = tid; i < 8192; i += 256) {
        int r = i >> 6, cp = i & 63;
        sWu[r*(NSTR/2) + cp] = __ldg(wsrc + i);
    }
    for (int i = tid; i < 8192; i += 256) {
        int m = i >> 6, kp = i & 63;
        int r = r0 + m; if (r >= NN) r = NN - 1;
        float2 v = __ldg((const float2*)(A + (size_t)r*HD) + kp);
        sAu[m*(NSTR/2) + kp] = pack_bf16x2(v.x, v.y);
    }
    __syncthreads();

    int lr = lane & 15, lc = (lane >> 4) << 3;
    float acc[16][4];
    #pragma unroll
    for (int i = 0; i < 16; i++)
        #pragma unroll
        for (int j = 0; j < 4; j++) acc[i][j] = 0.f;
    #pragma unroll
    for (int k0 = 0; k0 < 8; k0++) {
        uint32_t a[4];
        ldsm_x4(a, sbase + ((16*wid + lr)*NSTR + k0*16 + lc)*2);
        #pragma unroll
        for (int nt2 = 0; nt2 < 8; nt2++) {
            uint32_t b[4];
            ldsm_x4_t(b, sbase + O_NW + ((k0*16 + lr)*NSTR + nt2*16 + lc)*2);
            mma_bf16(acc[2*nt2],     a, b[0], b[1]);
            mma_bf16(acc[2*nt2 + 1], a, b[2], b[3]);
        }
    }

    int rA = r0 + 16*wid + (lane >> 2);
    int rB = rA + 8;
    int q = lane & 3;
    if (rA < NN) {
        float s = scaled ? g_dinv[rA] : 1.f;
        uint32_t* ob = (uint32_t*)outb + (size_t)rA*64;
        #pragma unroll
        for (int nt = 0; nt < 16; nt++)
            ob[nt*4 + q] = pack_bf16x2(acc[nt][0]*s, acc[nt][1]*s);
    }
    if (rB < NN) {
        float s = scaled ? g_dinv[rB] : 1.f;
        uint32_t* ob = (uint32_t*)outb + (size_t)rB*64;
        #pragma unroll
        for (int nt = 0; nt < 16; nt++)
            ob[nt*4 + q] = pack_bf16x2(acc[nt][2]*s, acc[nt][3]*s);
    }
}

// ---------------- CSR gather-aggregate (bf16 messages, unroll-4 MLP) ----------------
__global__ __launch_bounds__(256) void k_aggregate(const __nv_bfloat16* __restrict__ t,
        const float* __restrict__ b, float* __restrict__ outp) {
    int wid = threadIdx.x >> 5, lane = threadIdx.x & 31;
    int c = blockIdx.x * 8 + wid;
    int start = __ldg(&g_off[c]), end = __ldg(&g_off[c+1]);
    const uint2* T = (const uint2*)t;   // 32 uint2 per row (128 bf16)
    float ax = 0.f, ay = 0.f, az = 0.f, aw = 0.f;
    {   // self term
        uint2 sv = __ldg(T + (size_t)c*32 + lane);
        acc_bf16x2(sv.x, ax, ay);
        acc_bf16x2(sv.y, az, aw);
    }
    for (int base = start; base < end; base += 32) {
        int n = end - base;
        int myIdx = (lane < n) ? __ldg(&g_src[base + lane]) : 0;
        int cnt = min(32, n);
        int j = 0;
        for (; j + 4 <= cnt; j += 4) {
            int r0 = __shfl_sync(0xFFFFFFFFu, myIdx, j);
            int r1 = __shfl_sync(0xFFFFFFFFu, myIdx, j+1);
            int r2 = __shfl_sync(0xFFFFFFFFu, myIdx, j+2);
            int r3 = __shfl_sync(0xFFFFFFFFu, myIdx, j+3);
            uint2 v0 = __ldg(T + (size_t)r0*32 + lane);
            uint2 v1 = __ldg(T + (size_t)r1*32 + lane);
            uint2 v2 = __ldg(T + (size_t)r2*32 + lane);
            uint2 v3 = __ldg(T + (size_t)r3*32 + lane);
            acc_bf16x2(v0.x, ax, ay); acc_bf16x2(v0.y, az, aw);
            acc_bf16x2(v1.x, ax, ay); acc_bf16x2(v1.y, az, aw);
            acc_bf16x2(v2.x, ax, ay); acc_bf16x2(v2.y, az, aw);
            acc_bf16x2(v3.x, ax, ay); acc_bf16x2(v3.y, az, aw);
        }
        for (; j < cnt; j++) {
            int r = __shfl_sync(0xFFFFFFFFu, myIdx, j);
            uint2 v = __ldg(T + (size_t)r*32 + lane);
            acc_bf16x2(v.x, ax, ay);
            acc_bf16x2(v.y, az, aw);
        }
    }
    float d = g_dinv[c];
    float4 bb = __ldg((const float4*)b + lane);
    float4 o;
    o.x = fmaxf(d*ax + bb.x, 0.f);
    o.y = fmaxf(d*ay + bb.y, 0.f);
    o.z = fmaxf(d*az + bb.z, 0.f);
    o.w = fmaxf(d*aw + bb.w, 0.f);
    *((float4*)(outp + (size_t)c*HD) + lane) = o;
}

// ---------------- fused edge MLP: sync-free, register-chained mma ----------------
#define SAS 136
#define SBS 72
#define O_SB1   0          // 128 x 68 words
#define O_SB2   34816      // 128 x 36 words
#define O_SW0   53248      // 16 x 68 words (B0 augmented)
#define O_SC1P  57600      // 128 f32
#define O_SWC3  58112      // 128 f32
#define O_SBC2  58624      // 64 f32
#define SMEM_EDGE_BYTES 58880

__global__ __launch_bounds__(256, 2) void k_edge_mlp(
        const int* __restrict__ row, const int* __restrict__ col,
        const float* __restrict__ ea,
        const float* __restrict__ bc2, const float* __restrict__ Wc3,
        const float* __restrict__ bc3,
        const uint32_t* __restrict__ U, const uint32_t* __restrict__ V,
        float* __restrict__ out) {
    extern __shared__ char smem[];
    uint32_t sbase = smem_u32(smem);
    int tid = threadIdx.x;
    int wid = tid >> 5, lane = tid & 31;

    float* sC1p = (float*)(smem + O_SC1P);
    float* sWc3 = (float*)(smem + O_SWC3);
    float* sbc2 = (float*)(smem + O_SBC2);
    uint32_t* sB1u = (uint32_t*)(smem + O_SB1);
    uint32_t* sB2u = (uint32_t*)(smem + O_SB2);
    uint32_t* sW0u = (uint32_t*)(smem + O_SW0);

    // ---- persistent loads (once per block) ----
    if (tid < 128) {
        sC1p[tid] = g_c1p[tid];
        sWc3[tid] = __ldg(Wc3 + tid);
        if (tid < 64) sbc2[tid] = __ldg(bc2 + tid);
    }
    {
        const uint32_t* src = (const uint32_t*)g_B1;
        for (int i = tid; i < 8192; i += 256) {
            int r = i >> 6, cp = i & 63;
            sB1u[r*(SAS/2) + cp] = __ldg(src + i);
        }
    }
    {
        const uint32_t* src = (const uint32_t*)g_B2;
        for (int i = tid; i < 4096; i += 256) {
            int r = i >> 5, cp = i & 31;
            sB2u[r*(SBS/2) + cp] = __ldg(src + i);
        }
    }
    {
        const uint32_t* src = (const uint32_t*)g_B0;
        for (int i = tid; i < 1024; i += 256) {
            int r = i >> 6, cp = i & 63;
            sW0u[r*(SAS/2) + cp] = __ldg(src + i);
        }
    }
    __syncthreads();   // the only block-wide sync

    int lr = lane & 15, lc = (lane >> 4) << 3;
    int g = lane >> 2, t = lane & 3;
    float c3a = __ldg(bc3 + 0), c3b = __ldg(bc3 + 1);

    for (int wt = blockIdx.x*8 + wid; wt < NWT; wt += EGRID*8) {
        int e0 = wt * 16;
        int eA = e0 + g, eB = eA + 8;
        int rI0 = __ldg(row + eA), cI0 = __ldg(col + eA);
        int rI1 = __ldg(row + eB), cI1 = __ldg(col + eB);

        // ea A-fragments with augmented K (k=4 is the ones column -> bias)
        uint32_t eaf[4];
        eaf[2] = 0; eaf[3] = 0;
        if (t < 2) {
            float2 vA = *(const float2*)(ea + (size_t)eA*4 + 2*t);
            float2 vB = *(const float2*)(ea + (size_t)eB*4 + 2*t);
            eaf[0] = pack_bf16x2(vA.x, vA.y);
            eaf[1] = pack_bf16x2(vB.x, vB.y);
        } else if (t == 2) {
            eaf[0] = 0x00003F80u;   // (1.0, 0.0) bf16x2
            eaf[1] = 0x00003F80u;
        } else {
            eaf[0] = 0; eaf[1] = 0;
        }

        float acc[16][4];
        #pragma unroll
        for (int i = 0; i < 16; i++)
            #pragma unroll
            for (int j = 0; j < 4; j++) acc[i][j] = 0.f;

        // mma0: acc = [ea,1] @ [We1;be1]  (K=16, single k-step)
        #pragma unroll
        for (int nt2 = 0; nt2 < 8; nt2++) {
            uint32_t b[4];
            ldsm_x4_t(b, sbase + O_SW0 + (lr*SAS + nt2*16 + lc)*2);
            mma_bf16(acc[2*nt2],     eaf, b[0], b[1]);
            mma_bf16(acc[2*nt2 + 1], eaf, b[2], b[3]);
        }

        // relu -> A-fragments for GEMM1 (D->A register conversion)
        uint32_t af[8][4];
        #pragma unroll
        for (int kt = 0; kt < 8; kt++) {
            af[kt][0] = pack_bf16x2(fmaxf(acc[2*kt][0],   0.f), fmaxf(acc[2*kt][1],   0.f));
            af[kt][1] = pack_bf16x2(fmaxf(acc[2*kt][2],   0.f), fmaxf(acc[2*kt][3],   0.f));
            af[kt][2] = pack_bf16x2(fmaxf(acc[2*kt+1][0], 0.f), fmaxf(acc[2*kt+1][1], 0.f));
            af[kt][3] = pack_bf16x2(fmaxf(acc[2*kt+1][2], 0.f), fmaxf(acc[2*kt+1][3], 0.f));
        }

        // GEMM1: acc = a @ M
        #pragma unroll
        for (int i = 0; i < 16; i++)
            #pragma unroll
            for (int j = 0; j < 4; j++) acc[i][j] = 0.f;
        #pragma unroll
        for (int k0 = 0; k0 < 8; k0++) {
            #pragma unroll
            for (int nt2 = 0; nt2 < 8; nt2++) {
                uint32_t b[4];
                ldsm_x4_t(b, sbase + O_SB1 + ((k0*16 + lr)*SAS + nt2*16 + lc)*2);
                mma_bf16(acc[2*nt2],     af[k0], b[0], b[1]);
                mma_bf16(acc[2*nt2 + 1], af[k0], b[2], b[3]);
            }
        }

        // epilogue1: z1 = relu(acc + U[row] + V[col] + c1p) -> A-frags (in regs)
        {
            const uint32_t* U0 = U + (size_t)rI0*64;
            const uint32_t* V0 = V + (size_t)cI0*64;
            const uint32_t* U1 = U + (size_t)rI1*64;
            const uint32_t* V1 = V + (size_t)cI1*64;
            #pragma unroll
            for (int kt = 0; kt < 8; kt++) {
                int cw0 = kt*8 + t;
                int cw1 = kt*8 + 4 + t;
                uint32_t uA0 = __ldg(U0 + cw0), vA0 = __ldg(V0 + cw0);
                uint32_t uB0 = __ldg(U1 + cw0), vB0 = __ldg(V1 + cw0);
                uint32_t uA1 = __ldg(U0 + cw1), vA1 = __ldg(V0 + cw1);
                uint32_t uB1 = __ldg(U1 + cw1), vB1 = __ldg(V1 + cw1);
                int c0 = cw0*2, c1 = cw1*2;
                float p00 = sC1p[c0], p01 = sC1p[c0+1];
                float p10 = sC1p[c1], p11 = sC1p[c1+1];
                af[kt][0] = pack_bf16x2(
                    fmaxf(acc[2*kt][0] + bf_lo(uA0) + bf_lo(vA0) + p00, 0.f),
                    fmaxf(acc[2*kt][1] + bf_hi(uA0) + bf_hi(vA0) + p01, 0.f));
                af[kt][1] = pack_bf16x2(
                    fmaxf(acc[2*kt][2] + bf_lo(uB0) + bf_lo(vB0) + p00, 0.f),
                    fmaxf(acc[2*kt][3] + bf_hi(uB0) + bf_hi(vB0) + p01, 0.f));
                af[kt][2] = pack_bf16x2(
                    fmaxf(acc[2*kt+1][0] + bf_lo(uA1) + bf_lo(vA1) + p10, 0.f),
                    fmaxf(acc[2*kt+1][1] + bf_hi(uA1) + bf_hi(vA1) + p11, 0.f));
                af[kt][3] = pack_bf16x2(
                    fmaxf(acc[2*kt+1][2] + bf_lo(uB1) + bf_lo(vB1) + p10, 0.f),
                    fmaxf(acc[2*kt+1][3] + bf_hi(uB1) + bf_hi(vB1) + p11, 0.f));
            }
        }

        // GEMM2: acc[0..7] = z1 @ Wc2
        #pragma unroll
        for (int i = 0; i < 8; i++)
            #pragma unroll
            for (int j = 0; j < 4; j++) acc[i][j] = 0.f;
        #pragma unroll
        for (int k0 = 0; k0 < 8; k0++) {
            #pragma unroll
            for (int nt2 = 0; nt2 < 4; nt2++) {
                uint32_t b[4];
                ldsm_x4_t(b, sbase + O_SB2 + ((k0*16 + lr)*SBS + nt2*16 + lc)*2);
                mma_bf16(acc[2*nt2],     af[k0], b[0], b[1]);
                mma_bf16(acc[2*nt2 + 1], af[k0], b[2], b[3]);
            }
        }

        // epilogue2: z2 = relu(acc + bc2); logits; log_softmax
        {
            float l0a = 0.f, l1a = 0.f, l0b = 0.f, l1b = 0.f;
            #pragma unroll
            for (int nt = 0; nt < 8; nt++) {
                int c = nt*8 + 2*t;
                float b0 = sbc2[c], b1 = sbc2[c+1];
                float w00 = sWc3[2*c],   w01 = sWc3[2*c+1];
                float w10 = sWc3[2*c+2], w11 = sWc3[2*c+3];
                float za = fmaxf(acc[nt][0] + b0, 0.f);
                float zb = fmaxf(acc[nt][1] + b1, 0.f);
                l0a += za*w00 + zb*w10;
                l1a += za*w01 + zb*w11;
                float zc = fmaxf(acc[nt][2] + b0, 0.f);
                float zd = fmaxf(acc[nt][3] + b1, 0.f);
                l0b += zc*w00 + zd*w10;
                l1b += zc*w01 + zd*w11;
            }
            #pragma unroll
            for (int off = 1; off <= 2; off <<= 1) {
                l0a += __shfl_xor_sync(0xFFFFFFFFu, l0a, off);
                l1a += __shfl_xor_sync(0xFFFFFFFFu, l1a, off);
                l0b += __shfl_xor_sync(0xFFFFFFFFu, l0b, off);
                l1b += __shfl_xor_sync(0xFFFFFFFFu, l1b, off);
            }
            if (t == 0) {
                float L0 = l0a + c3a, L1 = l1a + c3b;
                float mx = fmaxf(L0, L1);
                float lse = mx + logf(expf(L0 - mx) + expf(L1 - mx));
                size_t o = (size_t)eA * 2;
                out[o + 0] = L0 - lse;
                out[o + 1] = L1 - lse;
                L0 = l0b + c3a; L1 = l1b + c3b;
                mx = fmaxf(L0, L1);
                lse = mx + logf(expf(L0 - mx) + expf(L1 - mx));
                o = (size_t)eB * 2;
                out[o + 0] = L0 - lse;
                out[o + 1] = L1 - lse;
            }
        }
    }
}

// ---------------- launch ----------------
extern "C" void kernel_launch(void* const* d_in, const int* in_sizes, int n_in,
                              void* d_out, int out_size) {
    const float* x   = (const float*)d_in[0];
    const int*   ei  = (const int*)  d_in[1];
    const float* ea  = (const float*)d_in[2];
    const float* W1  = (const float*)d_in[3];
    const float* b1  = (const float*)d_in[4];
    const float* W2  = (const float*)d_in[5];
    const float* b2  = (const float*)d_in[6];
    const float* W3  = (const float*)d_in[7];
    const float* b3  = (const float*)d_in[8];
    const float* We1 = (const float*)d_in[9];
    const float* be1 = (const float*)d_in[10];
    const float* We2 = (const float*)d_in[11];
    const float* be2 = (const float*)d_in[12];
    const float* Wc1 = (const float*)d_in[13];
    const float* bc1 = (const float*)d_in[14];
    const float* Wc2 = (const float*)d_in[15];
    const float* bc2 = (const float*)d_in[16];
    const float* Wc3 = (const float*)d_in[17];
    const float* bc3 = (const float*)d_in[18];
    float* out = (float*)d_out;
    const int* row = ei;
    const int* col = ei + NE;

    float *h1, *h2;
    __nv_bfloat16 *tb, *ub, *vb;
    cudaGetSymbolAddress((void**)&h1, g_h1);
    cudaGetSymbolAddress((void**)&h2, g_h2);
    cudaGetSymbolAddress((void**)&tb, g_tb);
    cudaGetSymbolAddress((void**)&ub, g_Ub);
    cudaGetSymbolAddress((void**)&vb, g_Vb);
    __nv_bfloat16 *wb2, *wb3, *wbu, *wbv;
    cudaGetSymbolAddress((void**)&wb2, g_Wb2);
    cudaGetSymbolAddress((void**)&wb3, g_Wb3);
    cudaGetSymbolAddress((void**)&wbu, g_WbU);
    cudaGetSymbolAddress((void**)&wbv, g_WbV);

    cudaFuncSetAttribute(k_node_mma, cudaFuncAttributeMaxDynamicSharedMemorySize, SMEM_NODE_BYTES);
    cudaFuncSetAttribute(k_edge_mlp, cudaFuncAttributeMaxDynamicSharedMemorySize, SMEM_EDGE_BYTES);

    // graph preprocessing
    k_deg_zero <<<(NN + 255)/256, 256>>>();
    k_deg_count<<<(NE + 255)/256, 256>>>(col);
    k_scanA    <<<NCHUNK, 1024>>>();
    k_scanB    <<<1, 64>>>();
    k_scanC    <<<(NN + 255)/256, 256>>>();
    k_fill     <<<(NE + 255)/256, 256>>>(row, col);
    k_prep     <<<360, 256>>>(We2, Wc1, be2, bc1, Wc2, W2, W3, We1, be1);

    const int NB = (NN + 127)/128;
    // layer 1
    k_transform1<<<(NN + 63)/64, 128>>>(x, W1, tb);
    k_aggregate <<<NN/8, 256>>>(tb, b1, h1);
    // layer 2
    k_node_mma  <<<NB, 256, SMEM_NODE_BYTES>>>(h1, wb2, tb, 1);
    k_aggregate <<<NN/8, 256>>>(tb, b2, h2);
    // layer 3
    k_node_mma  <<<NB, 256, SMEM_NODE_BYTES>>>(h2, wb3, tb, 1);
    k_aggregate <<<NN/8, 256>>>(tb, b3, h1);

    // U = h@Wc1[0:128], V = h@Wc1[128:256]  (bf16)
    k_node_mma  <<<NB, 256, SMEM_NODE_BYTES>>>(h1, wbu, ub, 0);
    k_node_mma  <<<NB, 256, SMEM_NODE_BYTES>>>(h1, wbv, vb, 0);

    k_edge_mlp<<<EGRID, 256, SMEM_EDGE_BYTES>>>(row, col, ea,
                                                bc2, Wc3, bc3,
                                                (const uint32_t*)ub, (const uint32_t*)vb, out);
}

// round 10
// speedup vs baseline: 6.1373x; 1.0506x over previous
#include <cuda_runtime.h>
#include <cuda_bf16.h>
#include <math.h>
#include <stdint.h>

#define NN 50000
#define NE 800000
#define HD 128
#define FNI 8
#define FEI 4
#define EGRID 296       // edge blocks = 148 SMs x occupancy 2 (fully resident)
#define NWT (NE/16)     // 50000 warp-tiles
#define NCHUNK 49       // ceil(NN/1024)

// ---------------- device scratch (no allocations allowed) ----------------
__device__ int   g_deg[NN];
__device__ int   g_off[NN+1];
__device__ int   g_cur[NN];
__device__ int   g_src[NE];
__device__ int   g_bsum[NCHUNK];
__device__ float g_dinv[NN];
__device__ __nv_bfloat16 g_h1[NN*HD];   // h accumulator A (bf16)
__device__ __nv_bfloat16 g_h2[NN*HD];   // h accumulator B (bf16)
__device__ __nv_bfloat16 g_tb[NN*HD];   // bf16 message buffer
__device__ __nv_bfloat16 g_Ub[NN*HD];   // bf16 U = h@Wc1[0:128]
__device__ __nv_bfloat16 g_Vb[NN*HD];   // bf16 V = h@Wc1[128:256]
__device__ float g_c1p[HD];    // bc1 + be2 @ Wc1[256:384]
__device__ __nv_bfloat16 g_B1[HD*HD];   // M = We2@Wc1c, row-major [k][n], bf16
__device__ __nv_bfloat16 g_B2[HD*64];   // Wc2 row-major [k][n], bf16
__device__ __nv_bfloat16 g_B0[16*HD];   // [We1; be1; 0] augmented-K, [k][n], bf16
__device__ __nv_bfloat16 g_Wb2[HD*HD];  // bf16 W2
__device__ __nv_bfloat16 g_Wb3[HD*HD];  // bf16 W3
__device__ __nv_bfloat16 g_WbU[HD*HD];  // bf16 Wc1[0:128]
__device__ __nv_bfloat16 g_WbV[HD*HD];  // bf16 Wc1[128:256]

// ---------------- PTX helpers ----------------
__device__ __forceinline__ uint32_t smem_u32(const void* p) {
    uint32_t a;
    asm("{ .reg .u64 t; cvta.to.shared.u64 t, %1; cvt.u32.u64 %0, t; }" : "=r"(a) : "l"(p));
    return a;
}
__device__ __forceinline__ void ldsm_x4(uint32_t* r, uint32_t addr) {
    asm volatile("ldmatrix.sync.aligned.m8n8.x4.shared.b16 {%0,%1,%2,%3}, [%4];"
        : "=r"(r[0]), "=r"(r[1]), "=r"(r[2]), "=r"(r[3]) : "r"(addr));
}
__device__ __forceinline__ void ldsm_x4_t(uint32_t* r, uint32_t addr) {
    asm volatile("ldmatrix.sync.aligned.m8n8.x4.trans.shared.b16 {%0,%1,%2,%3}, [%4];"
        : "=r"(r[0]), "=r"(r[1]), "=r"(r[2]), "=r"(r[3]) : "r"(addr));
}
__device__ __forceinline__ void mma_bf16(float* d, const uint32_t* a, uint32_t b0, uint32_t b1) {
    asm volatile("mma.sync.aligned.m16n8k16.row.col.f32.bf16.bf16.f32 "
        "{%0,%1,%2,%3}, {%4,%5,%6,%7}, {%8,%9}, {%0,%1,%2,%3};"
        : "+f"(d[0]), "+f"(d[1]), "+f"(d[2]), "+f"(d[3])
        : "r"(a[0]), "r"(a[1]), "r"(a[2]), "r"(a[3]), "r"(b0), "r"(b1));
}
__device__ __forceinline__ uint32_t pack_bf16x2(float lo, float hi) {
    uint32_t p;
    asm("cvt.rn.bf16x2.f32 %0, %1, %2;" : "=r"(p) : "f"(hi), "f"(lo));
    return p;
}
__device__ __forceinline__ void acc_bf16x2(uint32_t u, float& lo, float& hi) {
    lo += __uint_as_float(u << 16);
    hi += __uint_as_float(u & 0xFFFF0000u);
}
__device__ __forceinline__ float bf_lo(uint32_t u) { return __uint_as_float(u << 16); }
__device__ __forceinline__ float bf_hi(uint32_t u) { return __uint_as_float(u & 0xFFFF0000u); }

// ---------------- degree / norm / CSR ----------------
__global__ void k_deg_count(const int* __restrict__ col) {
    int i = blockIdx.x*blockDim.x + threadIdx.x;
    if (i < NE) atomicAdd(&g_deg[col[i]], 1);
}
__global__ __launch_bounds__(1024) void k_scanA() {
    __shared__ int ws[32];
    int tid = threadIdx.x, lane = tid & 31, w = tid >> 5;
    int i = blockIdx.x*1024 + tid;
    int v = (i < NN) ? g_deg[i] : 0;
    if (i < NN) g_dinv[i] = rsqrtf((float)(v + 1));  // +1 self loop
    int x = v;
    #pragma unroll
    for (int d = 1; d < 32; d <<= 1) {
        int y = __shfl_up_sync(0xFFFFFFFFu, x, d);
        if (lane >= d) x += y;
    }
    if (lane == 31) ws[w] = x;
    __syncthreads();
    if (w == 0) {
        int y = ws[lane];
        #pragma unroll
        for (int d = 1; d < 32; d <<= 1) {
            int z = __shfl_up_sync(0xFFFFFFFFu, y, d);
            if (lane >= d) y += z;
        }
        ws[lane] = y;
    }
    __syncthreads();
    int excl = x - v + (w > 0 ? ws[w-1] : 0);
    if (i < NN) g_off[i] = excl;
    if (tid == 1023) g_bsum[blockIdx.x] = ws[31];
}
__global__ void k_scanB() {
    __shared__ int wtot[2];
    int tid = threadIdx.x, lane = tid & 31, w = tid >> 5;
    int v = (tid < NCHUNK) ? g_bsum[tid] : 0;
    int x = v;
    #pragma unroll
    for (int d = 1; d < 32; d <<= 1) {
        int y = __shfl_up_sync(0xFFFFFFFFu, x, d);
        if (lane >= d) x += y;
    }
    if (lane == 31) wtot[w] = x;
    __syncthreads();
    if (w == 1) x += wtot[0];
    if (tid < NCHUNK) g_bsum[tid] = x - v;
    if (tid == 0) g_off[NN] = wtot[0] + wtot[1];
}
__global__ void k_scanC() {
    int i = blockIdx.x*blockDim.x + threadIdx.x;
    if (i < NN) {
        int o = g_off[i] + g_bsum[i >> 10];
        g_off[i] = o;
        g_cur[i] = o;
    }
}
__global__ void k_fill(const int* __restrict__ row, const int* __restrict__ col) {
    int i = blockIdx.x*blockDim.x + threadIdx.x;
    if (i < NE) {
        int pos = atomicAdd(&g_cur[col[i]], 1);
        g_src[pos] = row[i];
    }
}

// ---------------- precompute: folded weights + bf16 weights ----------------
__global__ void k_prep(const float* __restrict__ We2, const float* __restrict__ Wc1,
                       const float* __restrict__ be2, const float* __restrict__ bc1,
                       const float* __restrict__ Wc2, const float* __restrict__ W2,
                       const float* __restrict__ W3, const float* __restrict__ We1,
                       const float* __restrict__ be1) {
    int idx = blockIdx.x*256 + threadIdx.x;   // 0..92159
    const float* Wc1c = Wc1 + 256*HD;
    if (idx < 16384) {
        int k = idx >> 7, n = idx & 127;
        float s = 0.f;
        for (int j = 0; j < HD; j++) s += __ldg(We2 + k*HD + j) * __ldg(Wc1c + j*HD + n);
        g_B1[idx] = __float2bfloat16(s);
        if (idx < 128) {
            float c = __ldg(bc1 + idx);
            for (int j = 0; j < HD; j++) c += __ldg(be2 + j) * __ldg(Wc1c + j*HD + idx);
            g_c1p[idx] = c;
        }
    } else if (idx < 24576) {
        int t = idx - 16384;
        g_B2[t] = __float2bfloat16(__ldg(Wc2 + t));
    } else if (idx < 40960) {
        int t = idx - 24576;
        g_Wb2[t] = __float2bfloat16(__ldg(W2 + t));
    } else if (idx < 57344) {
        int t = idx - 40960;
        g_Wb3[t] = __float2bfloat16(__ldg(W3 + t));
    } else if (idx < 73728) {
        int t = idx - 57344;
        g_WbU[t] = __float2bfloat16(__ldg(Wc1 + t));
    } else if (idx < 90112) {
        int t = idx - 73728;
        g_WbV[t] = __float2bfloat16(__ldg(Wc1 + HD*HD + t));
    } else if (idx < 92160) {
        int e = idx - 90112;      // 16x128 augmented [We1; be1; 0]
        int k = e >> 7, n = e & 127;
        float v = (k < 4) ? __ldg(We1 + k*HD + n) : (k == 4 ? __ldg(be1 + n) : 0.f);
        g_B0[e] = __float2bfloat16(v);
    }
}

// ---------------- layer-1 transform (K=8): tb = bf16(dinv * (x@W1)) ----------------
__global__ void k_transform1(const float* __restrict__ x, const float* __restrict__ W1,
                             __nv_bfloat16* __restrict__ tout) {
    __shared__ float sx[64*FNI];
    __shared__ float sw[FNI*HD];
    int tid = threadIdx.x;  // 0..127
    for (int i = tid; i < FNI*HD; i += 128) sw[i] = W1[i];
    int r0 = blockIdx.x * 64;
    for (int i = tid; i < 64*FNI; i += 128) {
        int r = r0 + (i >> 3);
        sx[i] = (r < NN) ? x[r*FNI + (i & 7)] : 0.f;
    }
    __syncthreads();
    int c = (tid & 63) * 2;
    int half = tid >> 6;
    for (int m = half*32; m < half*32 + 32; m++) {
        int r = r0 + m;
        if (r >= NN) break;
        float a0 = 0.f, a1 = 0.f;
        #pragma unroll
        for (int k = 0; k < FNI; k++) {
            float xv = sx[m*FNI + k];
            a0 += xv * sw[k*HD + c];
            a1 += xv * sw[k*HD + c + 1];
        }
        float d = g_dinv[r];
        ((uint32_t*)tout)[(size_t)r*64 + (c >> 1)] = pack_bf16x2(d*a0, d*a1);
    }
}

// ---------------- node GEMM via mma.sync bf16 (bf16 A): outb = bf16((A@Wb) [*dinv]) ----------------
#define NSTR 136
#define O_NW 34816
#define SMEM_NODE_BYTES 69632

__global__ __launch_bounds__(256, 2) void k_node_mma(const __nv_bfloat16* __restrict__ A,
        const __nv_bfloat16* __restrict__ Wb,
        __nv_bfloat16* __restrict__ outb, int scaled) {
    extern __shared__ char smem[];
    uint32_t sbase = smem_u32(smem);
    uint32_t* sAu = (uint32_t*)smem;
    uint32_t* sWu = (uint32_t*)(smem + O_NW);
    int tid = threadIdx.x, wid = tid >> 5, lane = tid & 31;
    int r0 = blockIdx.x * 128;

    const uint32_t* wsrc = (const uint32_t*)Wb;
    const uint32_t* asrc = (const uint32_t*)A;
    for (int i = tid; i < 8192; i += 256) {
        int r = i >> 6, cp = i & 63;
        sWu[r*(NSTR/2) + cp] = __ldg(wsrc + i);
    }
    for (int i = tid; i < 8192; i += 256) {
        int m = i >> 6, kp = i & 63;
        int r = r0 + m; if (r >= NN) r = NN - 1;
        sAu[m*(NSTR/2) + kp] = __ldg(asrc + (size_t)r*64 + kp);
    }
    __syncthreads();

    int lr = lane & 15, lc = (lane >> 4) << 3;
    float acc[16][4];
    #pragma unroll
    for (int i = 0; i < 16; i++)
        #pragma unroll
        for (int j = 0; j < 4; j++) acc[i][j] = 0.f;
    #pragma unroll
    for (int k0 = 0; k0 < 8; k0++) {
        uint32_t a[4];
        ldsm_x4(a, sbase + ((16*wid + lr)*NSTR + k0*16 + lc)*2);
        #pragma unroll
        for (int nt2 = 0; nt2 < 8; nt2++) {
            uint32_t b[4];
            ldsm_x4_t(b, sbase + O_NW + ((k0*16 + lr)*NSTR + nt2*16 + lc)*2);
            mma_bf16(acc[2*nt2],     a, b[0], b[1]);
            mma_bf16(acc[2*nt2 + 1], a, b[2], b[3]);
        }
    }

    int rA = r0 + 16*wid + (lane >> 2);
    int rB = rA + 8;
    int q = lane & 3;
    if (rA < NN) {
        float s = scaled ? g_dinv[rA] : 1.f;
        uint32_t* ob = (uint32_t*)outb + (size_t)rA*64;
        #pragma unroll
        for (int nt = 0; nt < 16; nt++)
            ob[nt*4 + q] = pack_bf16x2(acc[nt][0]*s, acc[nt][1]*s);
    }
    if (rB < NN) {
        float s = scaled ? g_dinv[rB] : 1.f;
        uint32_t* ob = (uint32_t*)outb + (size_t)rB*64;
        #pragma unroll
        for (int nt = 0; nt < 16; nt++)
            ob[nt*4 + q] = pack_bf16x2(acc[nt][2]*s, acc[nt][3]*s);
    }
}

// ---------------- CSR gather-aggregate (bf16 in, bf16 out) ----------------
// h[c] = bf16(relu(dinv[c]*(sum msgs + self) + b))
__global__ __launch_bounds__(256) void k_aggregate(const __nv_bfloat16* __restrict__ t,
        const float* __restrict__ b, __nv_bfloat16* __restrict__ outp) {
    int wid = threadIdx.x >> 5, lane = threadIdx.x & 31;
    int c = blockIdx.x * 8 + wid;
    int start = __ldg(&g_off[c]), end = __ldg(&g_off[c+1]);
    const uint2* T = (const uint2*)t;   // 32 uint2 per row (128 bf16)
    float ax = 0.f, ay = 0.f, az = 0.f, aw = 0.f;
    {   // self term
        uint2 sv = __ldg(T + (size_t)c*32 + lane);
        acc_bf16x2(sv.x, ax, ay);
        acc_bf16x2(sv.y, az, aw);
    }
    for (int base = start; base < end; base += 32) {
        int n = end - base;
        int myIdx = (lane < n) ? __ldg(&g_src[base + lane]) : 0;
        int cnt = min(32, n);
        int j = 0;
        for (; j + 4 <= cnt; j += 4) {
            int r0 = __shfl_sync(0xFFFFFFFFu, myIdx, j);
            int r1 = __shfl_sync(0xFFFFFFFFu, myIdx, j+1);
            int r2 = __shfl_sync(0xFFFFFFFFu, myIdx, j+2);
            int r3 = __shfl_sync(0xFFFFFFFFu, myIdx, j+3);
            uint2 v0 = __ldg(T + (size_t)r0*32 + lane);
            uint2 v1 = __ldg(T + (size_t)r1*32 + lane);
            uint2 v2 = __ldg(T + (size_t)r2*32 + lane);
            uint2 v3 = __ldg(T + (size_t)r3*32 + lane);
            acc_bf16x2(v0.x, ax, ay); acc_bf16x2(v0.y, az, aw);
            acc_bf16x2(v1.x, ax, ay); acc_bf16x2(v1.y, az, aw);
            acc_bf16x2(v2.x, ax, ay); acc_bf16x2(v2.y, az, aw);
            acc_bf16x2(v3.x, ax, ay); acc_bf16x2(v3.y, az, aw);
        }
        for (; j < cnt; j++) {
            int r = __shfl_sync(0xFFFFFFFFu, myIdx, j);
            uint2 v = __ldg(T + (size_t)r*32 + lane);
            acc_bf16x2(v.x, ax, ay);
            acc_bf16x2(v.y, az, aw);
        }
    }
    float d = g_dinv[c];
    float4 bb = __ldg((const float4*)b + lane);
    uint2 o;
    o.x = pack_bf16x2(fmaxf(d*ax + bb.x, 0.f), fmaxf(d*ay + bb.y, 0.f));
    o.y = pack_bf16x2(fmaxf(d*az + bb.z, 0.f), fmaxf(d*aw + bb.w, 0.f));
    ((uint2*)outp)[(size_t)c*32 + lane] = o;
}

// ---------------- fused edge MLP: sync-free, register-chained mma ----------------
#define SAS 136
#define SBS 72
#define O_SB1   0          // 128 x 68 words
#define O_SB2   34816      // 128 x 36 words
#define O_SW0   53248      // 16 x 68 words (B0 augmented)
#define O_SC1P  57600      // 128 f32
#define O_SWC3  58112      // 128 f32
#define O_SBC2  58624      // 64 f32
#define SMEM_EDGE_BYTES 58880

__global__ __launch_bounds__(256, 2) void k_edge_mlp(
        const int* __restrict__ row, const int* __restrict__ col,
        const float* __restrict__ ea,
        const float* __restrict__ bc2, const float* __restrict__ Wc3,
        const float* __restrict__ bc3,
        const uint32_t* __restrict__ U, const uint32_t* __restrict__ V,
        float* __restrict__ out) {
    extern __shared__ char smem[];
    uint32_t sbase = smem_u32(smem);
    int tid = threadIdx.x;
    int wid = tid >> 5, lane = tid & 31;

    float* sC1p = (float*)(smem + O_SC1P);
    float* sWc3 = (float*)(smem + O_SWC3);
    float* sbc2 = (float*)(smem + O_SBC2);
    uint32_t* sB1u = (uint32_t*)(smem + O_SB1);
    uint32_t* sB2u = (uint32_t*)(smem + O_SB2);
    uint32_t* sW0u = (uint32_t*)(smem + O_SW0);

    // ---- persistent loads (once per block) ----
    if (tid < 128) {
        sC1p[tid] = g_c1p[tid];
        sWc3[tid] = __ldg(Wc3 + tid);
        if (tid < 64) sbc2[tid] = __ldg(bc2 + tid);
    }
    {
        const uint32_t* src = (const uint32_t*)g_B1;
        for (int i = tid; i < 8192; i += 256) {
            int r = i >> 6, cp = i & 63;
            sB1u[r*(SAS/2) + cp] = __ldg(src + i);
        }
    }
    {
        const uint32_t* src = (const uint32_t*)g_B2;
        for (int i = tid; i < 4096; i += 256) {
            int r = i >> 5, cp = i & 31;
            sB2u[r*(SBS/2) + cp] = __ldg(src + i);
        }
    }
    {
        const uint32_t* src = (const uint32_t*)g_B0;
        for (int i = tid; i < 1024; i += 256) {
            int r = i >> 6, cp = i & 63;
            sW0u[r*(SAS/2) + cp] = __ldg(src + i);
        }
    }
    __syncthreads();   // the only block-wide sync

    int lr = lane & 15, lc = (lane >> 4) << 3;
    int g = lane >> 2, t = lane & 3;
    float c3a = __ldg(bc3 + 0), c3b = __ldg(bc3 + 1);

    for (int wt = blockIdx.x*8 + wid; wt < NWT; wt += EGRID*8) {
        int e0 = wt * 16;
        int eA = e0 + g, eB = eA + 8;
        int rI0 = __ldg(row + eA), cI0 = __ldg(col + eA);
        int rI1 = __ldg(row + eB), cI1 = __ldg(col + eB);

        // ea A-fragments with augmented K (k=4 is the ones column -> bias)
        uint32_t eaf[4];
        eaf[2] = 0; eaf[3] = 0;
        if (t < 2) {
            float2 vA = *(const float2*)(ea + (size_t)eA*4 + 2*t);
            float2 vB = *(const float2*)(ea + (size_t)eB*4 + 2*t);
            eaf[0] = pack_bf16x2(vA.x, vA.y);
            eaf[1] = pack_bf16x2(vB.x, vB.y);
        } else if (t == 2) {
            eaf[0] = 0x00003F80u;   // (1.0, 0.0) bf16x2
            eaf[1] = 0x00003F80u;
        } else {
            eaf[0] = 0; eaf[1] = 0;
        }

        float acc[16][4];
        #pragma unroll
        for (int i = 0; i < 16; i++)
            #pragma unroll
            for (int j = 0; j < 4; j++) acc[i][j] = 0.f;

        // mma0: acc = [ea,1] @ [We1;be1]  (K=16, single k-step)
        #pragma unroll
        for (int nt2 = 0; nt2 < 8; nt2++) {
            uint32_t b[4];
            ldsm_x4_t(b, sbase + O_SW0 + (lr*SAS + nt2*16 + lc)*2);
            mma_bf16(acc[2*nt2],     eaf, b[0], b[1]);
            mma_bf16(acc[2*nt2 + 1], eaf, b[2], b[3]);
        }

        // relu -> A-fragments for GEMM1 (D->A register conversion)
        uint32_t af[8][4];
        #pragma unroll
        for (int kt = 0; kt < 8; kt++) {
            af[kt][0] = pack_bf16x2(fmaxf(acc[2*kt][0],   0.f), fmaxf(acc[2*kt][1],   0.f));
            af[kt][1] = pack_bf16x2(fmaxf(acc[2*kt][2],   0.f), fmaxf(acc[2*kt][3],   0.f));
            af[kt][2] = pack_bf16x2(fmaxf(acc[2*kt+1][0], 0.f), fmaxf(acc[2*kt+1][1], 0.f));
            af[kt][3] = pack_bf16x2(fmaxf(acc[2*kt+1][2], 0.f), fmaxf(acc[2*kt+1][3], 0.f));
        }

        // GEMM1: acc = a @ M
        #pragma unroll
        for (int i = 0; i < 16; i++)
            #pragma unroll
            for (int j = 0; j < 4; j++) acc[i][j] = 0.f;
        #pragma unroll
        for (int k0 = 0; k0 < 8; k0++) {
            #pragma unroll
            for (int nt2 = 0; nt2 < 8; nt2++) {
                uint32_t b[4];
                ldsm_x4_t(b, sbase + O_SB1 + ((k0*16 + lr)*SAS + nt2*16 + lc)*2);
                mma_bf16(acc[2*nt2],     af[k0], b[0], b[1]);
                mma_bf16(acc[2*nt2 + 1], af[k0], b[2], b[3]);
            }
        }

        // epilogue1: z1 = relu(acc + U[row] + V[col] + c1p) -> A-frags (in regs)
        {
            const uint32_t* U0 = U + (size_t)rI0*64;
            const uint32_t* V0 = V + (size_t)cI0*64;
            const uint32_t* U1 = U + (size_t)rI1*64;
            const uint32_t* V1 = V + (size_t)cI1*64;
            #pragma unroll
            for (int kt = 0; kt < 8; kt++) {
                int cw0 = kt*8 + t;
                int cw1 = kt*8 + 4 + t;
                uint32_t uA0 = __ldg(U0 + cw0), vA0 = __ldg(V0 + cw0);
                uint32_t uB0 = __ldg(U1 + cw0), vB0 = __ldg(V1 + cw0);
                uint32_t uA1 = __ldg(U0 + cw1), vA1 = __ldg(V0 + cw1);
                uint32_t uB1 = __ldg(U1 + cw1), vB1 = __ldg(V1 + cw1);
                int c0 = cw0*2, c1 = cw1*2;
                float p00 = sC1p[c0], p01 = sC1p[c0+1];
                float p10 = sC1p[c1], p11 = sC1p[c1+1];
                af[kt][0] = pack_bf16x2(
                    fmaxf(acc[2*kt][0] + bf_lo(uA0) + bf_lo(vA0) + p00, 0.f),
                    fmaxf(acc[2*kt][1] + bf_hi(uA0) + bf_hi(vA0) + p01, 0.f));
                af[kt][1] = pack_bf16x2(
                    fmaxf(acc[2*kt][2] + bf_lo(uB0) + bf_lo(vB0) + p00, 0.f),
                    fmaxf(acc[2*kt][3] + bf_hi(uB0) + bf_hi(vB0) + p01, 0.f));
                af[kt][2] = pack_bf16x2(
                    fmaxf(acc[2*kt+1][0] + bf_lo(uA1) + bf_lo(vA1) + p10, 0.f),
                    fmaxf(acc[2*kt+1][1] + bf_hi(uA1) + bf_hi(vA1) + p11, 0.f));
                af[kt][3] = pack_bf16x2(
                    fmaxf(acc[2*kt+1][2] + bf_lo(uB1) + bf_lo(vB1) + p10, 0.f),
                    fmaxf(acc[2*kt+1][3] + bf_hi(uB1) + bf_hi(vB1) + p11, 0.f));
            }
        }

        // GEMM2: acc[0..7] = z1 @ Wc2
        #pragma unroll
        for (int i = 0; i < 8; i++)
            #pragma unroll
            for (int j = 0; j < 4; j++) acc[i][j] = 0.f;
        #pragma unroll
        for (int k0 = 0; k0 < 8; k0++) {
            #pragma unroll
            for (int nt2 = 0; nt2 < 4; nt2++) {
                uint32_t b[4];
                ldsm_x4_t(b, sbase + O_SB2 + ((k0*16 + lr)*SBS + nt2*16 + lc)*2);
                mma_bf16(acc[2*nt2],     af[k0], b[0], b[1]);
                mma_bf16(acc[2*nt2 + 1], af[k0], b[2], b[3]);
            }
        }

        // epilogue2: z2 = relu(acc + bc2); logits; log_softmax
        {
            float l0a = 0.f, l1a = 0.f, l0b = 0.f, l1b = 0.f;
            #pragma unroll
            for (int nt = 0; nt < 8; nt++) {
                int c = nt*8 + 2*t;
                float b0 = sbc2[c], b1 = sbc2[c+1];
                float w00 = sWc3[2*c],   w01 = sWc3[2*c+1];
                float w10 = sWc3[2*c+2], w11 = sWc3[2*c+3];
                float za = fmaxf(acc[nt][0] + b0, 0.f);
                float zb = fmaxf(acc[nt][1] + b1, 0.f);
                l0a += za*w00 + zb*w10;
                l1a += za*w01 + zb*w11;
                float zc = fmaxf(acc[nt][2] + b0, 0.f);
                float zd = fmaxf(acc[nt][3] + b1, 0.f);
                l0b += zc*w00 + zd*w10;
                l1b += zc*w01 + zd*w11;
            }
            #pragma unroll
            for (int off = 1; off <= 2; off <<= 1) {
                l0a += __shfl_xor_sync(0xFFFFFFFFu, l0a, off);
                l1a += __shfl_xor_sync(0xFFFFFFFFu, l1a, off);
                l0b += __shfl_xor_sync(0xFFFFFFFFu, l0b, off);
                l1b += __shfl_xor_sync(0xFFFFFFFFu, l1b, off);
            }
            if (t == 0) {
                float L0 = l0a + c3a, L1 = l1a + c3b;
                float mx = fmaxf(L0, L1);
                float lse = mx + logf(expf(L0 - mx) + expf(L1 - mx));
                size_t o = (size_t)eA * 2;
                out[o + 0] = L0 - lse;
                out[o + 1] = L1 - lse;
                L0 = l0b + c3a; L1 = l1b + c3b;
                mx = fmaxf(L0, L1);
                lse = mx + logf(expf(L0 - mx) + expf(L1 - mx));
                o = (size_t)eB * 2;
                out[o + 0] = L0 - lse;
                out[o + 1] = L1 - lse;
            }
        }
    }
}

// ---------------- launch ----------------
extern "C" void kernel_launch(void* const* d_in, const int* in_sizes, int n_in,
                              void* d_out, int out_size) {
    const float* x   = (const float*)d_in[0];
    const int*   ei  = (const int*)  d_in[1];
    const float* ea  = (const float*)d_in[2];
    const float* W1  = (const float*)d_in[3];
    const float* b1  = (const float*)d_in[4];
    const float* W2  = (const float*)d_in[5];
    const float* b2  = (const float*)d_in[6];
    const float* W3  = (const float*)d_in[7];
    const float* b3  = (const float*)d_in[8];
    const float* We1 = (const float*)d_in[9];
    const float* be1 = (const float*)d_in[10];
    const float* We2 = (const float*)d_in[11];
    const float* be2 = (const float*)d_in[12];
    const float* Wc1 = (const float*)d_in[13];
    const float* bc1 = (const float*)d_in[14];
    const float* Wc2 = (const float*)d_in[15];
    const float* bc2 = (const float*)d_in[16];
    const float* Wc3 = (const float*)d_in[17];
    const float* bc3 = (const float*)d_in[18];
    float* out = (float*)d_out;
    const int* row = ei;
    const int* col = ei + NE;

    __nv_bfloat16 *h1, *h2, *tb, *ub, *vb;
    cudaGetSymbolAddress((void**)&h1, g_h1);
    cudaGetSymbolAddress((void**)&h2, g_h2);
    cudaGetSymbolAddress((void**)&tb, g_tb);
    cudaGetSymbolAddress((void**)&ub, g_Ub);
    cudaGetSymbolAddress((void**)&vb, g_Vb);
    __nv_bfloat16 *wb2, *wb3, *wbu, *wbv;
    cudaGetSymbolAddress((void**)&wb2, g_Wb2);
    cudaGetSymbolAddress((void**)&wb3, g_Wb3);
    cudaGetSymbolAddress((void**)&wbu, g_WbU);
    cudaGetSymbolAddress((void**)&wbv, g_WbV);
    int* degp;
    cudaGetSymbolAddress((void**)&degp, g_deg);

    cudaFuncSetAttribute(k_node_mma, cudaFuncAttributeMaxDynamicSharedMemorySize, SMEM_NODE_BYTES);
    cudaFuncSetAttribute(k_edge_mlp, cudaFuncAttributeMaxDynamicSharedMemorySize, SMEM_EDGE_BYTES);

    // graph preprocessing
    cudaMemsetAsync(degp, 0, NN*sizeof(int));
    k_deg_count<<<(NE + 255)/256, 256>>>(col);
    k_scanA    <<<NCHUNK, 1024>>>();
    k_scanB    <<<1, 64>>>();
    k_scanC    <<<(NN + 255)/256, 256>>>();
    k_fill     <<<(NE + 255)/256, 256>>>(row, col);
    k_prep     <<<360, 256>>>(We2, Wc1, be2, bc1, Wc2, W2, W3, We1, be1);

    const int NB = (NN + 127)/128;
    // layer 1
    k_transform1<<<(NN + 63)/64, 128>>>(x, W1, tb);
    k_aggregate <<<NN/8, 256>>>(tb, b1, h1);
    // layer 2
    k_node_mma  <<<NB, 256, SMEM_NODE_BYTES>>>(h1, wb2, tb, 1);
    k_aggregate <<<NN/8, 256>>>(tb, b2, h2);
    // layer 3
    k_node_mma  <<<NB, 256, SMEM_NODE_BYTES>>>(h2, wb3, tb, 1);
    k_aggregate <<<NN/8, 256>>>(tb, b3, h1);

    // U = h@Wc1[0:128], V = h@Wc1[128:256]  (bf16)
    k_node_mma  <<<NB, 256, SMEM_NODE_BYTES>>>(h1, wbu, ub, 0);
    k_node_mma  <<<NB, 256, SMEM_NODE_BYTES>>>(h1, wbv, vb, 0);

    k_edge_mlp<<<EGRID, 256, SMEM_EDGE_BYTES>>>(row, col, ea,
                                                bc2, Wc3, bc3,
                                                (const uint32_t*)ub, (const uint32_t*)vb, out);
}